// round 14
// baseline (speedup 1.0000x reference)
#include <cuda_runtime.h>

// Shapes fixed by the problem
#define BB 16
#define XL 1024
#define YL 1024
#define DD 1024
#define NEG_INF (-1e20f)

// ---------------------------------------------------------------------------
// Warp-specialized pipeline, 256 threads/CTA (warps 0-3 consumers with 64x64
// warp tiles, warps 4-7 producers), 3-stage smem ring.
// scores stage: {A_HI,A_LO,B_HI,B_LO} 16KB each = 64KB; 3 stages + mask+stats.
// emb    stage: {A_HI,A_LO,B_HI}      16KB each = 48KB; 3 stages.
// Tiles: 128 rows x 128B, SW128-swizzled, K-major.
// Softmax is fused: scores writes raw masked scores to scratch + per-tile
// (max,sumexp) stats; reduce kernel folds stats per row; emb producers apply
// exp((s-m))*inv on the fly and bx==0 CTAs write normalized weights to d_out.
// ---------------------------------------------------------------------------
#define OFF_A_HI 0
#define OFF_A_LO 16384
#define OFF_B_HI 32768
#define OFF_B_LO 49152
#define S_STAGE 65536
#define S_OFF_MASK (3 * S_STAGE)
#define S_OFF_STATS (S_OFF_MASK + 512)
#define S_SMEM_BYTES (S_OFF_STATS + 2048)

#define E_STAGE 49152
#define E_SMEM_BYTES (3 * E_STAGE)

#define NBAR_THREADS 256

// Scratch (device globals are the sanctioned scratch path)
__device__ float g_scratch[(size_t)BB * XL * YL];          // raw masked scores
__device__ float2 g_stats[BB * XL][8];                      // per-tile (m, sumexp)
__device__ float2 g_rowstats[BB * XL];                      // per-row (m, 1/sum)

// ---------------------------------------------------------------------------
// Helpers
// ---------------------------------------------------------------------------
static __device__ __forceinline__ unsigned smem_u32(const void* p) {
    unsigned a;
    asm("{ .reg .u64 t; cvta.to.shared.u64 t, %1; cvt.u32.u64 %0, t; }"
        : "=r"(a) : "l"(p));
    return a;
}
static __device__ __forceinline__ float tf32_rna(float x) {
    unsigned u;
    asm("cvt.rna.tf32.f32 %0, %1;" : "=r"(u) : "f"(x));
    return __uint_as_float(u);
}
static __device__ __forceinline__ void split4(float4 v, float4& h, float4& l) {
    h.x = tf32_rna(v.x); l.x = tf32_rna(v.x - h.x);
    h.y = tf32_rna(v.y); l.y = tf32_rna(v.y - h.y);
    h.z = tf32_rna(v.z); l.z = tf32_rna(v.z - h.z);
    h.w = tf32_rna(v.w); l.w = tf32_rna(v.w - h.w);
}
static __device__ __forceinline__ float4 hi4(float4 v) {
    float4 h;
    h.x = tf32_rna(v.x); h.y = tf32_rna(v.y);
    h.z = tf32_rna(v.z); h.w = tf32_rna(v.w);
    return h;
}
static __device__ __forceinline__ void bar_sync(int id) {
    asm volatile("bar.sync %0, %1;" :: "r"(id), "n"(NBAR_THREADS) : "memory");
}
static __device__ __forceinline__ void bar_arrive(int id) {
    asm volatile("bar.arrive %0, %1;" :: "r"(id), "n"(NBAR_THREADS) : "memory");
}
static __device__ __forceinline__ void bar_sync_half(int id) {
    asm volatile("bar.sync %0, %1;" :: "r"(id), "n"(128) : "memory");
}

#define LDSM_X4(r, addr)                                                      \
    asm volatile(                                                             \
        "ldmatrix.sync.aligned.m8n8.x4.shared.b16 {%0,%1,%2,%3}, [%4];"       \
        : "=r"((r)[0]), "=r"((r)[1]), "=r"((r)[2]), "=r"((r)[3])              \
        : "r"(addr))

#define MMA_TF32(d, a, b0, b1)                                                \
    asm volatile(                                                             \
        "mma.sync.aligned.m16n8k8.row.col.f32.tf32.tf32.f32 "                 \
        "{%0,%1,%2,%3}, {%4,%5,%6,%7}, {%8,%9}, {%0,%1,%2,%3};"               \
        : "+f"((d)[0]), "+f"((d)[1]), "+f"((d)[2]), "+f"((d)[3])              \
        : "r"((a)[0]), "r"((a)[1]), "r"((a)[2]), "r"((a)[3]),                 \
          "r"(b0), "r"(b1))

// ---------------------------------------------------------------------------
// Consumer MMA over one resident K-chunk. 4 warps, warp tile 64x64:
// 4 m16 x 8 n8 tiles. 3 products (hh, lh, hl). 384 MMAs / chunk / warp.
// ---------------------------------------------------------------------------
static __device__ __forceinline__ void mma_chunk3(
    unsigned base, unsigned aRow, unsigned bRow,
    const unsigned colA[4], const unsigned colB[4], float acc[4][8][4])
{
    unsigned fa[4][4], fb[4][4], fl[4][4], fbl[4][4];
#pragma unroll
    for (int k8 = 0; k8 < 4; ++k8) {
#pragma unroll
        for (int i = 0; i < 4; ++i)
            LDSM_X4(fa[i], base + OFF_A_HI + aRow + 2048u * i + colA[k8]);
#pragma unroll
        for (int jp = 0; jp < 4; ++jp)
            LDSM_X4(fb[jp], base + OFF_B_HI + bRow + 2048u * jp + colB[k8]);
#pragma unroll
        for (int i = 0; i < 4; ++i)
            LDSM_X4(fl[i], base + OFF_A_LO + aRow + 2048u * i + colA[k8]);
#pragma unroll
        for (int jp = 0; jp < 4; ++jp)
            LDSM_X4(fbl[jp], base + OFF_B_LO + bRow + 2048u * jp + colB[k8]);

        // hi*hi
#pragma unroll
        for (int i = 0; i < 4; ++i)
#pragma unroll
            for (int j = 0; j < 8; ++j)
                MMA_TF32(acc[i][j], fa[i], fb[j >> 1][(j & 1) * 2],
                         fb[j >> 1][(j & 1) * 2 + 1]);
        // lo*hi
#pragma unroll
        for (int i = 0; i < 4; ++i)
#pragma unroll
            for (int j = 0; j < 8; ++j)
                MMA_TF32(acc[i][j], fl[i], fb[j >> 1][(j & 1) * 2],
                         fb[j >> 1][(j & 1) * 2 + 1]);
        // hi*lo
#pragma unroll
        for (int i = 0; i < 4; ++i)
#pragma unroll
            for (int j = 0; j < 8; ++j)
                MMA_TF32(acc[i][j], fa[i], fbl[j >> 1][(j & 1) * 2],
                         fbl[j >> 1][(j & 1) * 2 + 1]);
    }
}

// 2 products (hh, lh) — emb path: full-A x B_hi.
static __device__ __forceinline__ void mma_chunk2(
    unsigned base, unsigned aRow, unsigned bRow,
    const unsigned colA[4], const unsigned colB[4], float acc[4][8][4])
{
    unsigned fa[4][4], fb[4][4], fl[4][4];
#pragma unroll
    for (int k8 = 0; k8 < 4; ++k8) {
#pragma unroll
        for (int i = 0; i < 4; ++i)
            LDSM_X4(fa[i], base + OFF_A_HI + aRow + 2048u * i + colA[k8]);
#pragma unroll
        for (int jp = 0; jp < 4; ++jp)
            LDSM_X4(fb[jp], base + OFF_B_HI + bRow + 2048u * jp + colB[k8]);
#pragma unroll
        for (int i = 0; i < 4; ++i)
            LDSM_X4(fl[i], base + OFF_A_LO + aRow + 2048u * i + colA[k8]);

#pragma unroll
        for (int i = 0; i < 4; ++i)
#pragma unroll
            for (int j = 0; j < 8; ++j)
                MMA_TF32(acc[i][j], fa[i], fb[j >> 1][(j & 1) * 2],
                         fb[j >> 1][(j & 1) * 2 + 1]);
#pragma unroll
        for (int i = 0; i < 4; ++i)
#pragma unroll
            for (int j = 0; j < 8; ++j)
                MMA_TF32(acc[i][j], fl[i], fb[j >> 1][(j & 1) * 2],
                         fb[j >> 1][(j & 1) * 2 + 1]);
    }
}

// online-softmax pair combine
static __device__ __forceinline__ void comb(float& m, float& s, float mo, float so) {
    float mn = fmaxf(m, mo);
    s = s * __expf(m - mn) + so * __expf(mo - mn);
    m = mn;
}

// ---------------------------------------------------------------------------
// Kernel 1: raw masked scores -> g_scratch, per-tile (max,sumexp) -> g_stats.
// ---------------------------------------------------------------------------
__global__ __launch_bounds__(256, 1)
void scores_tc_kernel(const float* __restrict__ xs,
                      const float* __restrict__ ys,
                      const int* __restrict__ mask)
{
    extern __shared__ char smem[];
    const unsigned sb = smem_u32(smem);
    const int t = threadIdx.x;
    const int wid = t >> 5;
    const int lane = t & 31;
    const int b = blockIdx.z;
    const int rowBase = blockIdx.y * 128;
    const int colBase = blockIdx.x * 128;

    const float* A  = xs + (size_t)b * XL * DD + (size_t)rowBase * DD;
    const float* Bp = ys + (size_t)b * YL * DD + (size_t)colBase * DD;

    if (wid >= 4) {
        // ---------------- producer warps (4..7) ----------------
        const int pt = t - 128;   // 0..127
        ((int*)(smem + S_OFF_MASK))[pt] = mask[b * YL + colBase + pt];

        int lr[8], lc4[8];
        unsigned loff[8];
#pragma unroll
        for (int i = 0; i < 8; ++i) {
            int s = pt + i * 128;
            lr[i]  = s >> 3;
            lc4[i] = s & 7;
            loff[i] = (unsigned)lr[i] * 128u +
                      (((unsigned)lc4[i] * 16u) ^ (((unsigned)(lr[i] & 7)) << 4));
        }

        float4 pa[8], pb[8];
#pragma unroll
        for (int i = 0; i < 8; ++i) {
            pa[i] = *reinterpret_cast<const float4*>(A  + (size_t)lr[i] * DD + lc4[i] * 4);
            pb[i] = *reinterpret_cast<const float4*>(Bp + (size_t)lr[i] * DD + lc4[i] * 4);
        }

        for (int c = 0; c < 32; ++c) {
            const int s = c - (c / 3) * 3;         // c % 3
            char* st = smem + s * S_STAGE;
            if (c >= 3) bar_sync(4 + s);
#pragma unroll
            for (int i = 0; i < 8; ++i) {
                float4 h, l;
                split4(pa[i], h, l);
                *reinterpret_cast<float4*>(st + OFF_A_HI + loff[i]) = h;
                *reinterpret_cast<float4*>(st + OFF_A_LO + loff[i]) = l;
                split4(pb[i], h, l);
                *reinterpret_cast<float4*>(st + OFF_B_HI + loff[i]) = h;
                *reinterpret_cast<float4*>(st + OFF_B_LO + loff[i]) = l;
            }
            __threadfence_block();
            bar_arrive(1 + s);
            if (c < 31) {
                const int k0 = (c + 1) * 32;
#pragma unroll
                for (int i = 0; i < 8; ++i) {
                    pa[i] = *reinterpret_cast<const float4*>(A  + (size_t)lr[i] * DD + k0 + lc4[i] * 4);
                    pb[i] = *reinterpret_cast<const float4*>(Bp + (size_t)lr[i] * DD + k0 + lc4[i] * 4);
                }
            }
        }
        return;
    }

    // ---------------- consumer warps (0..3), 64x64 tiles ----------------
    const int m0 = (wid & 1) * 64;
    const int n0 = (wid >> 1) * 64;

    const unsigned xr = (unsigned)(lane & 7) << 4;
    const unsigned rA = (unsigned)((lane & 7) + ((lane >> 3) & 1) * 8);
    const unsigned cA = (unsigned)((lane >> 4) << 4);
    const unsigned rB = (unsigned)((lane & 7) + ((lane >> 4) & 1) * 8);
    const unsigned cB = (unsigned)(((lane >> 3) & 1) << 4);
    const unsigned aRow = ((unsigned)m0 + rA) * 128u;
    const unsigned bRow = ((unsigned)n0 + rB) * 128u;
    unsigned colA[4], colB[4];
#pragma unroll
    for (int k8 = 0; k8 < 4; ++k8) {
        colA[k8] = ((unsigned)(k8 * 32) + cA) ^ xr;
        colB[k8] = ((unsigned)(k8 * 32) + cB) ^ xr;
    }

    float acc[4][8][4];
#pragma unroll
    for (int i = 0; i < 4; ++i)
#pragma unroll
        for (int j = 0; j < 8; ++j)
#pragma unroll
            for (int d = 0; d < 4; ++d) acc[i][j][d] = 0.0f;

    for (int c = 0; c < 32; ++c) {
        const int s = c - (c / 3) * 3;
        bar_sync(1 + s);
        mma_chunk3(sb + (unsigned)s * S_STAGE, aRow, bRow, colA, colB, acc);
        bar_arrive(4 + s);
    }

    // epilogue: masked raw scores -> scratch; per-row (max, sumexp) stats
    const int* ms = (const int*)(smem + S_OFF_MASK);
    float2* stat = (float2*)(smem + S_OFF_STATS);   // [128][2]
    float* sc = g_scratch + (size_t)b * XL * YL + (size_t)rowBase * YL + colBase;
    const int g = lane >> 2;
    const int cp = (lane & 3) * 2;
    const int wcol = wid >> 1;

#pragma unroll
    for (int i = 0; i < 4; ++i) {
        const int rowL = m0 + 16 * i + g;
        float mL = NEG_INF, mH = NEG_INF;
#pragma unroll
        for (int j = 0; j < 8; ++j) {
            const int col = n0 + 8 * j + cp;
            const int mk0 = ms[col];
            const int mk1 = ms[col + 1];
            float v0 = mk0 ? acc[i][j][0] : NEG_INF;
            float v1 = mk1 ? acc[i][j][1] : NEG_INF;
            float v2 = mk0 ? acc[i][j][2] : NEG_INF;
            float v3 = mk1 ? acc[i][j][3] : NEG_INF;
            float2 w0; w0.x = v0; w0.y = v1;
            float2 w1; w1.x = v2; w1.y = v3;
            *reinterpret_cast<float2*>(sc + (size_t)rowL * YL + col) = w0;
            *reinterpret_cast<float2*>(sc + (size_t)(rowL + 8) * YL + col) = w1;
            mL = fmaxf(mL, fmaxf(v0, v1));
            mH = fmaxf(mH, fmaxf(v2, v3));
        }
        float sL = 0.0f, sH = 0.0f;
#pragma unroll
        for (int j = 0; j < 8; ++j) {
            const int col = n0 + 8 * j + cp;
            const int mk0 = ms[col];
            const int mk1 = ms[col + 1];
            float v0 = mk0 ? acc[i][j][0] : NEG_INF;
            float v1 = mk1 ? acc[i][j][1] : NEG_INF;
            float v2 = mk0 ? acc[i][j][2] : NEG_INF;
            float v3 = mk1 ? acc[i][j][3] : NEG_INF;
            sL += __expf(v0 - mL) + __expf(v1 - mL);
            sH += __expf(v2 - mH) + __expf(v3 - mH);
        }
        // reduce across the 4 lanes sharing each row
#pragma unroll
        for (int d = 1; d < 4; d <<= 1) {
            float mo = __shfl_xor_sync(0xFFFFFFFFu, mL, d);
            float so = __shfl_xor_sync(0xFFFFFFFFu, sL, d);
            comb(mL, sL, mo, so);
            mo = __shfl_xor_sync(0xFFFFFFFFu, mH, d);
            so = __shfl_xor_sync(0xFFFFFFFFu, sH, d);
            comb(mH, sH, mo, so);
        }
        if ((lane & 3) == 0) {
            float2 v; v.x = mL; v.y = sL;
            stat[rowL * 2 + wcol] = v;
            v.x = mH; v.y = sH;
            stat[(rowL + 8) * 2 + wcol] = v;
        }
    }
    bar_sync_half(7);
    // combine the two n-halves; one thread per row
    {
        float2 a = stat[t * 2 + 0];
        float2 bb = stat[t * 2 + 1];
        comb(a.x, a.y, bb.x, bb.y);
        g_stats[b * XL + rowBase + t][blockIdx.x] = a;
    }
}

// ---------------------------------------------------------------------------
// Kernel 2: fold per-tile stats into per-row (max, 1/sum)
// ---------------------------------------------------------------------------
__global__ __launch_bounds__(256)
void reduce_stats_kernel()
{
    const int r = blockIdx.x * 256 + threadIdx.x;
    float2 st[8];
#pragma unroll
    for (int i = 0; i < 8; ++i) st[i] = g_stats[r][i];
    float m = st[0].x;
#pragma unroll
    for (int i = 1; i < 8; ++i) m = fmaxf(m, st[i].x);
    float s = 0.0f;
#pragma unroll
    for (int i = 0; i < 8; ++i) s += st[i].y * __expf(st[i].x - m);
    float2 o; o.x = m; o.y = 1.0f / s;
    g_rowstats[r] = o;
}

// ---------------------------------------------------------------------------
// Kernel 3: emb = softmax(scores) @ ys. Producers apply exp((s-m))*inv on the
// fly; bx==0 CTAs also write the normalized weights to d_out.
// ---------------------------------------------------------------------------
__global__ __launch_bounds__(256, 1)
void emb_tc_kernel(const float* __restrict__ ys,
                   float* __restrict__ emb,
                   float* __restrict__ wout)
{
    extern __shared__ char smem[];
    const unsigned sb = smem_u32(smem);
    const int t = threadIdx.x;
    const int wid = t >> 5;
    const int lane = t & 31;
    const int b = blockIdx.z;
    const int rowBase = blockIdx.y * 128;   // x
    const int colBase = blockIdx.x * 128;   // d

    const float* A   = g_scratch + (size_t)b * XL * YL + (size_t)rowBase * YL;
    const float* Byb = ys + (size_t)b * YL * DD + colBase;

    if (wid >= 4) {
        // ---------------- producer warps ----------------
        const int pt = t - 128;   // 0..127
        const bool wb = (blockIdx.x == 0);

        int lr[8], lc4[8];
        unsigned loff[8];
#pragma unroll
        for (int i = 0; i < 8; ++i) {
            int s = pt + i * 128;
            lr[i]  = s >> 3;
            lc4[i] = s & 7;
            loff[i] = (unsigned)lr[i] * 128u +
                      (((unsigned)lc4[i] * 16u) ^ (((unsigned)(lr[i] & 7)) << 4));
        }
        float2 rs[8];
#pragma unroll
        for (int i = 0; i < 8; ++i)
            rs[i] = g_rowstats[b * XL + rowBase + lr[i]];

        // B transpose-gather: thread owns d-col pt; 8 float4 of k values.
        unsigned tboff[8];
#pragma unroll
        for (int q = 0; q < 8; ++q)
            tboff[q] = (unsigned)pt * 128u +
                       (((unsigned)(q * 16)) ^ (((unsigned)(pt & 7)) << 4));

        float* wrow = wout + (size_t)b * XL * YL + (size_t)rowBase * YL;

        float4 pa[8], pb[8];
#pragma unroll
        for (int i = 0; i < 8; ++i)
            pa[i] = *reinterpret_cast<const float4*>(A + (size_t)lr[i] * YL + lc4[i] * 4);
        {
            const float* bp = Byb + pt;
#pragma unroll
            for (int q = 0; q < 8; ++q) {
                pb[q].x = bp[(size_t)(q * 4 + 0) * DD];
                pb[q].y = bp[(size_t)(q * 4 + 1) * DD];
                pb[q].z = bp[(size_t)(q * 4 + 2) * DD];
                pb[q].w = bp[(size_t)(q * 4 + 3) * DD];
            }
        }

        for (int c = 0; c < 32; ++c) {
            const int s = c - (c / 3) * 3;
            char* st = smem + s * E_STAGE;
            const int k0c = c * 32;
            if (c >= 3) bar_sync(4 + s);
#pragma unroll
            for (int i = 0; i < 8; ++i) {
                float4 e;
                e.x = __expf(pa[i].x - rs[i].x) * rs[i].y;
                e.y = __expf(pa[i].y - rs[i].x) * rs[i].y;
                e.z = __expf(pa[i].z - rs[i].x) * rs[i].y;
                e.w = __expf(pa[i].w - rs[i].x) * rs[i].y;
                float4 h, l;
                split4(e, h, l);
                *reinterpret_cast<float4*>(st + OFF_A_HI + loff[i]) = h;
                *reinterpret_cast<float4*>(st + OFF_A_LO + loff[i]) = l;
                if (wb)
                    *reinterpret_cast<float4*>(
                        wrow + (size_t)lr[i] * YL + k0c + lc4[i] * 4) = e;
            }
#pragma unroll
            for (int q = 0; q < 8; ++q) {
                *reinterpret_cast<float4*>(st + OFF_B_HI + tboff[q]) = hi4(pb[q]);
            }
            __threadfence_block();
            bar_arrive(1 + s);
            if (c < 31) {
                const int k0 = (c + 1) * 32;
#pragma unroll
                for (int i = 0; i < 8; ++i)
                    pa[i] = *reinterpret_cast<const float4*>(A + (size_t)lr[i] * YL + k0 + lc4[i] * 4);
                const float* bp = Byb + (size_t)k0 * DD + pt;
#pragma unroll
                for (int q = 0; q < 8; ++q) {
                    pb[q].x = bp[(size_t)(q * 4 + 0) * DD];
                    pb[q].y = bp[(size_t)(q * 4 + 1) * DD];
                    pb[q].z = bp[(size_t)(q * 4 + 2) * DD];
                    pb[q].w = bp[(size_t)(q * 4 + 3) * DD];
                }
            }
        }
        return;
    }

    // ---------------- consumer warps, 64x64 tiles ----------------
    const int m0 = (wid & 1) * 64;
    const int n0 = (wid >> 1) * 64;

    const unsigned xr = (unsigned)(lane & 7) << 4;
    const unsigned rA = (unsigned)((lane & 7) + ((lane >> 3) & 1) * 8);
    const unsigned cA = (unsigned)((lane >> 4) << 4);
    const unsigned rB = (unsigned)((lane & 7) + ((lane >> 4) & 1) * 8);
    const unsigned cB = (unsigned)(((lane >> 3) & 1) << 4);
    const unsigned aRow = ((unsigned)m0 + rA) * 128u;
    const unsigned bRow = ((unsigned)n0 + rB) * 128u;
    unsigned colA[4], colB[4];
#pragma unroll
    for (int k8 = 0; k8 < 4; ++k8) {
        colA[k8] = ((unsigned)(k8 * 32) + cA) ^ xr;
        colB[k8] = ((unsigned)(k8 * 32) + cB) ^ xr;
    }

    float acc[4][8][4];
#pragma unroll
    for (int i = 0; i < 4; ++i)
#pragma unroll
        for (int j = 0; j < 8; ++j)
#pragma unroll
            for (int d = 0; d < 4; ++d) acc[i][j][d] = 0.0f;

    for (int c = 0; c < 32; ++c) {
        const int s = c - (c / 3) * 3;
        bar_sync(1 + s);
        mma_chunk2(sb + (unsigned)s * E_STAGE, aRow, bRow, colA, colB, acc);
        bar_arrive(4 + s);
    }

    float* obase = emb + (size_t)b * XL * DD + colBase;
    const int g = lane >> 2;
    const int cp = (lane & 3) * 2;
#pragma unroll
    for (int i = 0; i < 4; ++i) {
        const int row = rowBase + m0 + 16 * i + g;
#pragma unroll
        for (int j = 0; j < 8; ++j) {
            const int col = n0 + 8 * j + cp;
            float2 v;
            v.x = acc[i][j][0];
            v.y = acc[i][j][1];
            *reinterpret_cast<float2*>(obase + (size_t)row * DD + col) = v;
            v.x = acc[i][j][2];
            v.y = acc[i][j][3];
            *reinterpret_cast<float2*>(obase + (size_t)(row + 8) * DD + col) = v;
        }
    }
}

// ---------------------------------------------------------------------------
extern "C" void kernel_launch(void* const* d_in, const int* in_sizes, int n_in,
                              void* d_out, int out_size)
{
    const float* xs   = (const float*)d_in[0];
    const float* ys   = (const float*)d_in[1];
    const int*   mask = (const int*)d_in[2];

    float* emb = (float*)d_out;                           // [B, XL, D]
    float* w   = (float*)d_out + (size_t)BB * XL * DD;    // [B, XL, YL]

    cudaFuncSetAttribute(scores_tc_kernel,
                         cudaFuncAttributeMaxDynamicSharedMemorySize, S_SMEM_BYTES);
    cudaFuncSetAttribute(emb_tc_kernel,
                         cudaFuncAttributeMaxDynamicSharedMemorySize, E_SMEM_BYTES);

    dim3 block(256);
    scores_tc_kernel<<<dim3(8, 8, BB), block, S_SMEM_BYTES>>>(xs, ys, mask);
    reduce_stats_kernel<<<(BB * XL) / 256, 256>>>();
    emb_tc_kernel<<<dim3(8, 8, BB), block, E_SMEM_BYTES>>>(ys, emb, w);
}

// round 15
// speedup vs baseline: 1.4539x; 1.4539x over previous
#include <cuda_runtime.h>

// Shapes fixed by the problem
#define BB 16
#define XL 1024
#define YL 1024
#define DD 1024
#define NEG_INF (-1e20f)

// ---------------------------------------------------------------------------
// Mask-compacted attention.
//  compact:  per-batch prefix scan of mask -> g_idx (unmasked y list), g_cnt
//  gather:   g_ys_c[b][j][:] = ys[b][g_idx[b][j]][:], zero-padded to 128
//  zerofill: weight output region -> 0 (masked cols never rewritten)
//  scores:   xs @ ys_c^T over compacted N (CTAs beyond nc_pad exit);
//            raw scores -> g_scratch (NEG_INF beyond cnt), per-tile stats
//  reduce:   fold per-tile (m,sum) -> per-row (m, 1/sum)
//  emb:      softmax(scratch) @ ys_c with K = nc_pad (runtime, ~half);
//            producers apply exp((s-m))*inv; bx==0 scatters weights via idx.
// GEMM config (best measured, R10/R11): 384 thr = 8 consumer warps (64x32
// tiles) + 4 producer warps, 3-stage SW128 K-major smem ring.
// ---------------------------------------------------------------------------
#define OFF_A_HI 0
#define OFF_A_LO 16384
#define OFF_B_HI 32768
#define OFF_B_LO 49152
#define S_STAGE 65536
#define S_OFF_STATS (3 * S_STAGE)              // 128 rows x 4 float2 = 4KB
#define S_SMEM_BYTES (S_OFF_STATS + 4096)

#define E_STAGE 49152
#define E_OFF_IDX (3 * E_STAGE)                // 1024 ints = 4KB
#define E_SMEM_BYTES (E_OFF_IDX + 4096)

#define NBAR_THREADS 384

// Device-global scratch (sanctioned path; no allocations)
__device__ float  g_scratch[(size_t)BB * XL * YL];   // raw compacted scores
__device__ float  g_ys_c[(size_t)BB * YL * DD];      // compacted ys
__device__ int    g_idx[BB][YL];                     // compacted -> original y
__device__ int    g_cnt[BB];                         // unmasked count per batch
__device__ float2 g_stats[BB * XL][8];               // per-tile (m, sumexp)
__device__ float2 g_rowstats[BB * XL];               // per-row (m, 1/sum)

// ---------------------------------------------------------------------------
// Helpers
// ---------------------------------------------------------------------------
static __device__ __forceinline__ unsigned smem_u32(const void* p) {
    unsigned a;
    asm("{ .reg .u64 t; cvta.to.shared.u64 t, %1; cvt.u32.u64 %0, t; }"
        : "=r"(a) : "l"(p));
    return a;
}
static __device__ __forceinline__ float tf32_rna(float x) {
    unsigned u;
    asm("cvt.rna.tf32.f32 %0, %1;" : "=r"(u) : "f"(x));
    return __uint_as_float(u);
}
static __device__ __forceinline__ void split4(float4 v, float4& h, float4& l) {
    h.x = tf32_rna(v.x); l.x = tf32_rna(v.x - h.x);
    h.y = tf32_rna(v.y); l.y = tf32_rna(v.y - h.y);
    h.z = tf32_rna(v.z); l.z = tf32_rna(v.z - h.z);
    h.w = tf32_rna(v.w); l.w = tf32_rna(v.w - h.w);
}
static __device__ __forceinline__ float4 hi4(float4 v) {
    float4 h;
    h.x = tf32_rna(v.x); h.y = tf32_rna(v.y);
    h.z = tf32_rna(v.z); h.w = tf32_rna(v.w);
    return h;
}
static __device__ __forceinline__ void bar_sync(int id) {
    asm volatile("bar.sync %0, %1;" :: "r"(id), "n"(NBAR_THREADS) : "memory");
}
static __device__ __forceinline__ void bar_arrive(int id) {
    asm volatile("bar.arrive %0, %1;" :: "r"(id), "n"(NBAR_THREADS) : "memory");
}
static __device__ __forceinline__ void bar_sync_n(int id, int n) {
    asm volatile("bar.sync %0, %1;" :: "r"(id), "r"(n) : "memory");
}

#define LDSM_X4(r, addr)                                                      \
    asm volatile(                                                             \
        "ldmatrix.sync.aligned.m8n8.x4.shared.b16 {%0,%1,%2,%3}, [%4];"       \
        : "=r"((r)[0]), "=r"((r)[1]), "=r"((r)[2]), "=r"((r)[3])              \
        : "r"(addr))

#define MMA_TF32(d, a, b0, b1)                                                \
    asm volatile(                                                             \
        "mma.sync.aligned.m16n8k8.row.col.f32.tf32.tf32.f32 "                 \
        "{%0,%1,%2,%3}, {%4,%5,%6,%7}, {%8,%9}, {%0,%1,%2,%3};"               \
        : "+f"((d)[0]), "+f"((d)[1]), "+f"((d)[2]), "+f"((d)[3])              \
        : "r"((a)[0]), "r"((a)[1]), "r"((a)[2]), "r"((a)[3]),                 \
          "r"(b0), "r"(b1))

// ---------------------------------------------------------------------------
// Consumer MMA over one K-chunk. 8 warps, warp tile 64x32 (4 m16 x 4 n8).
// ---------------------------------------------------------------------------
static __device__ __forceinline__ void mma_chunk3(
    unsigned base, unsigned aRow, unsigned bRow,
    const unsigned colA[4], const unsigned colB[4], float acc[4][4][4])
{
    unsigned fa[4][4], fb[2][4], fc[4][4];
#pragma unroll
    for (int k8 = 0; k8 < 4; ++k8) {
#pragma unroll
        for (int i = 0; i < 4; ++i)
            LDSM_X4(fa[i], base + OFF_A_HI + aRow + 2048u * i + colA[k8]);
#pragma unroll
        for (int jp = 0; jp < 2; ++jp)
            LDSM_X4(fb[jp], base + OFF_B_HI + bRow + 2048u * jp + colB[k8]);
#pragma unroll
        for (int i = 0; i < 4; ++i)
            LDSM_X4(fc[i], base + OFF_A_LO + aRow + 2048u * i + colA[k8]);

        // hi*hi
#pragma unroll
        for (int i = 0; i < 4; ++i)
#pragma unroll
            for (int j = 0; j < 4; ++j)
                MMA_TF32(acc[i][j], fa[i], fb[j >> 1][(j & 1) * 2],
                         fb[j >> 1][(j & 1) * 2 + 1]);
        // lo*hi
#pragma unroll
        for (int i = 0; i < 4; ++i)
#pragma unroll
            for (int j = 0; j < 4; ++j)
                MMA_TF32(acc[i][j], fc[i], fb[j >> 1][(j & 1) * 2],
                         fb[j >> 1][(j & 1) * 2 + 1]);
        // hi*lo
#pragma unroll
        for (int jp = 0; jp < 2; ++jp)
            LDSM_X4(fc[jp], base + OFF_B_LO + bRow + 2048u * jp + colB[k8]);
#pragma unroll
        for (int i = 0; i < 4; ++i)
#pragma unroll
            for (int j = 0; j < 4; ++j)
                MMA_TF32(acc[i][j], fa[i], fc[j >> 1][(j & 1) * 2],
                         fc[j >> 1][(j & 1) * 2 + 1]);
    }
}

// 2 products (hh, lh) — emb path: full-A x B_hi.
static __device__ __forceinline__ void mma_chunk2(
    unsigned base, unsigned aRow, unsigned bRow,
    const unsigned colA[4], const unsigned colB[4], float acc[4][4][4])
{
    unsigned fa[4][4], fb[2][4], fc[4][4];
#pragma unroll
    for (int k8 = 0; k8 < 4; ++k8) {
#pragma unroll
        for (int i = 0; i < 4; ++i)
            LDSM_X4(fa[i], base + OFF_A_HI + aRow + 2048u * i + colA[k8]);
#pragma unroll
        for (int jp = 0; jp < 2; ++jp)
            LDSM_X4(fb[jp], base + OFF_B_HI + bRow + 2048u * jp + colB[k8]);
#pragma unroll
        for (int i = 0; i < 4; ++i)
            LDSM_X4(fc[i], base + OFF_A_LO + aRow + 2048u * i + colA[k8]);

#pragma unroll
        for (int i = 0; i < 4; ++i)
#pragma unroll
            for (int j = 0; j < 4; ++j)
                MMA_TF32(acc[i][j], fa[i], fb[j >> 1][(j & 1) * 2],
                         fb[j >> 1][(j & 1) * 2 + 1]);
#pragma unroll
        for (int i = 0; i < 4; ++i)
#pragma unroll
            for (int j = 0; j < 4; ++j)
                MMA_TF32(acc[i][j], fc[i], fb[j >> 1][(j & 1) * 2],
                         fb[j >> 1][(j & 1) * 2 + 1]);
    }
}

// online-softmax pair combine
static __device__ __forceinline__ void comb(float& m, float& s, float mo, float so) {
    float mn = fmaxf(m, mo);
    s = s * __expf(m - mn) + so * __expf(mo - mn);
    m = mn;
}

// ---------------------------------------------------------------------------
// compact: one block per batch; inclusive scan of mask -> idx list + count
// ---------------------------------------------------------------------------
__global__ __launch_bounds__(1024)
void compact_kernel(const int* __restrict__ mask)
{
    __shared__ int s[1024];
    const int b = blockIdx.x;
    const int t = threadIdx.x;
    const int mk = mask[b * YL + t];
    s[t] = mk;
    __syncthreads();
#pragma unroll
    for (int off = 1; off < 1024; off <<= 1) {
        int v = (t >= off) ? s[t - off] : 0;
        __syncthreads();
        s[t] += v;
        __syncthreads();
    }
    if (mk) g_idx[b][s[t] - 1] = t;
    if (t == 1023) g_cnt[b] = s[1023];
}

// ---------------------------------------------------------------------------
// gather: g_ys_c[b][j][:] = ys[b][idx[j]][:]; zero rows [cnt, nc_pad)
// ---------------------------------------------------------------------------
__global__ __launch_bounds__(256)
void gather_kernel(const float* __restrict__ ys)
{
    const int b = blockIdx.y;
    const int t = threadIdx.x;
    const int cnt = g_cnt[b];
    const int ncp = (cnt + 127) & ~127;
    for (int r = 0; r < 16; ++r) {
        const int j = blockIdx.x * 16 + r;
        if (j >= ncp) break;
        float4 v = make_float4(0.f, 0.f, 0.f, 0.f);
        if (j < cnt) {
            const int y = g_idx[b][j];
            v = *reinterpret_cast<const float4*>(ys + ((size_t)b * YL + y) * DD + t * 4);
        }
        *reinterpret_cast<float4*>(g_ys_c + ((size_t)b * YL + j) * DD + t * 4) = v;
    }
}

// ---------------------------------------------------------------------------
// zerofill: weight output region -> 0
// ---------------------------------------------------------------------------
__global__ __launch_bounds__(256)
void zerofill_kernel(float* __restrict__ w)
{
    const size_t i = ((size_t)blockIdx.x * 256 + threadIdx.x) * 16;
    float4 z = make_float4(0.f, 0.f, 0.f, 0.f);
#pragma unroll
    for (int q = 0; q < 4; ++q)
        *reinterpret_cast<float4*>(w + i + q * 4) = z;
}

// ---------------------------------------------------------------------------
// scores: xs @ ys_c^T; raw scores -> g_scratch; per-tile stats -> g_stats
// ---------------------------------------------------------------------------
__global__ __launch_bounds__(384, 1)
void scores_tc_kernel(const float* __restrict__ xs)
{
    extern __shared__ char smem[];
    const unsigned sb = smem_u32(smem);
    const int t = threadIdx.x;
    const int wid = t >> 5;
    const int lane = t & 31;
    const int b = blockIdx.z;
    const int rowBase = blockIdx.y * 128;
    const int colBase = blockIdx.x * 128;

    const int cnt = g_cnt[b];
    const int ncp = (cnt + 127) & ~127;
    if (colBase >= ncp) return;            // uniform early exit, no barriers yet

    const float* A  = xs + (size_t)b * XL * DD + (size_t)rowBase * DD;
    const float* Bp = g_ys_c + (size_t)b * YL * DD + (size_t)colBase * DD;

    if (wid >= 8) {
        // ---------------- producer warps (8..11) ----------------
        const int pt = t - 256;   // 0..127

        int lr[8], lc4[8];
        unsigned loff[8];
#pragma unroll
        for (int i = 0; i < 8; ++i) {
            int s = pt + i * 128;
            lr[i]  = s >> 3;
            lc4[i] = s & 7;
            loff[i] = (unsigned)lr[i] * 128u +
                      (((unsigned)lc4[i] * 16u) ^ (((unsigned)(lr[i] & 7)) << 4));
        }

        float4 pa[8], pb[8];
#pragma unroll
        for (int i = 0; i < 8; ++i) {
            pa[i] = *reinterpret_cast<const float4*>(A  + (size_t)lr[i] * DD + lc4[i] * 4);
            pb[i] = *reinterpret_cast<const float4*>(Bp + (size_t)lr[i] * DD + lc4[i] * 4);
        }

        int s = 0;
        for (int c = 0; c < 32; ++c) {
            char* st = smem + s * S_STAGE;
            if (c >= 3) bar_sync(4 + s);
#pragma unroll
            for (int i = 0; i < 8; ++i) {
                float4 h, l;
                split4(pa[i], h, l);
                *reinterpret_cast<float4*>(st + OFF_A_HI + loff[i]) = h;
                *reinterpret_cast<float4*>(st + OFF_A_LO + loff[i]) = l;
                split4(pb[i], h, l);
                *reinterpret_cast<float4*>(st + OFF_B_HI + loff[i]) = h;
                *reinterpret_cast<float4*>(st + OFF_B_LO + loff[i]) = l;
            }
            __threadfence_block();
            bar_arrive(1 + s);
            if (c < 31) {
                const int k0 = (c + 1) * 32;
#pragma unroll
                for (int i = 0; i < 8; ++i) {
                    pa[i] = *reinterpret_cast<const float4*>(A  + (size_t)lr[i] * DD + k0 + lc4[i] * 4);
                    pb[i] = *reinterpret_cast<const float4*>(Bp + (size_t)lr[i] * DD + k0 + lc4[i] * 4);
                }
            }
            s = (s == 2) ? 0 : s + 1;
        }
        return;
    }

    // ---------------- consumer warps (0..7) ----------------
    const int m0 = (wid & 1) * 64;
    const int n0 = (wid >> 1) * 32;

    const unsigned xr = (unsigned)(lane & 7) << 4;
    const unsigned rA = (unsigned)((lane & 7) + ((lane >> 3) & 1) * 8);
    const unsigned cA = (unsigned)((lane >> 4) << 4);
    const unsigned rB = (unsigned)((lane & 7) + ((lane >> 4) & 1) * 8);
    const unsigned cB = (unsigned)(((lane >> 3) & 1) << 4);
    const unsigned aRow = ((unsigned)m0 + rA) * 128u;
    const unsigned bRow = ((unsigned)n0 + rB) * 128u;
    unsigned colA[4], colB[4];
#pragma unroll
    for (int k8 = 0; k8 < 4; ++k8) {
        colA[k8] = ((unsigned)(k8 * 32) + cA) ^ xr;
        colB[k8] = ((unsigned)(k8 * 32) + cB) ^ xr;
    }

    float acc[4][4][4];
#pragma unroll
    for (int i = 0; i < 4; ++i)
#pragma unroll
        for (int j = 0; j < 4; ++j)
#pragma unroll
            for (int d = 0; d < 4; ++d) acc[i][j][d] = 0.0f;

    int s = 0;
    for (int c = 0; c < 32; ++c) {
        bar_sync(1 + s);
        mma_chunk3(sb + (unsigned)s * S_STAGE, aRow, bRow, colA, colB, acc);
        bar_arrive(4 + s);
        s = (s == 2) ? 0 : s + 1;
    }

    // epilogue: raw scores -> scratch (NEG_INF beyond cnt); per-row stats
    float2* stat = (float2*)(smem + S_OFF_STATS);   // [128][4]
    float* sc = g_scratch + (size_t)b * XL * YL + (size_t)rowBase * YL + colBase;
    const int g = lane >> 2;
    const int cp = (lane & 3) * 2;
    const int nwid = wid >> 1;
    const int lim = cnt - colBase;                  // valid cols in this tile

#pragma unroll
    for (int i = 0; i < 4; ++i) {
        const int rowL = m0 + 16 * i + g;
        float mL = NEG_INF, mH = NEG_INF;
        float sL = 0.0f, sH = 0.0f;
        float v0s[4], v1s[4], v2s[4], v3s[4];
#pragma unroll
        for (int j = 0; j < 4; ++j) {
            const int col = n0 + 8 * j + cp;
            const bool ok0 = col < lim;
            const bool ok1 = (col + 1) < lim;
            float v0 = ok0 ? acc[i][j][0] : NEG_INF;
            float v1 = ok1 ? acc[i][j][1] : NEG_INF;
            float v2 = ok0 ? acc[i][j][2] : NEG_INF;
            float v3 = ok1 ? acc[i][j][3] : NEG_INF;
            v0s[j] = v0; v1s[j] = v1; v2s[j] = v2; v3s[j] = v3;
            float2 w0; w0.x = v0; w0.y = v1;
            float2 w1; w1.x = v2; w1.y = v3;
            *reinterpret_cast<float2*>(sc + (size_t)rowL * YL + col) = w0;
            *reinterpret_cast<float2*>(sc + (size_t)(rowL + 8) * YL + col) = w1;
            mL = fmaxf(mL, fmaxf(v0, v1));
            mH = fmaxf(mH, fmaxf(v2, v3));
        }
#pragma unroll
        for (int j = 0; j < 4; ++j) {
            sL += __expf(v0s[j] - mL) + __expf(v1s[j] - mL);
            sH += __expf(v2s[j] - mH) + __expf(v3s[j] - mH);
        }
        // reduce across the 4 lanes sharing each row
#pragma unroll
        for (int d = 1; d < 4; d <<= 1) {
            float mo = __shfl_xor_sync(0xFFFFFFFFu, mL, d);
            float so = __shfl_xor_sync(0xFFFFFFFFu, sL, d);
            comb(mL, sL, mo, so);
            mo = __shfl_xor_sync(0xFFFFFFFFu, mH, d);
            so = __shfl_xor_sync(0xFFFFFFFFu, sH, d);
            comb(mH, sH, mo, so);
        }
        if ((lane & 3) == 0) {
            float2 v; v.x = mL; v.y = sL;
            stat[rowL * 4 + nwid] = v;
            v.x = mH; v.y = sH;
            stat[(rowL + 8) * 4 + nwid] = v;
        }
    }
    bar_sync_n(7, 256);                // consumer warps only
    if (t < 128) {
        float2 a = stat[t * 4 + 0];
#pragma unroll
        for (int q = 1; q < 4; ++q) {
            float2 o = stat[t * 4 + q];
            comb(a.x, a.y, o.x, o.y);
        }
        g_stats[b * XL + rowBase + t][blockIdx.x] = a;
    }
}

// ---------------------------------------------------------------------------
// reduce: fold active per-tile stats into per-row (max, 1/sum)
// ---------------------------------------------------------------------------
__global__ __launch_bounds__(256)
void reduce_stats_kernel()
{
    const int r = blockIdx.x * 256 + threadIdx.x;
    const int b = r >> 10;
    const int nt = (g_cnt[b] + 127) >> 7;
    float2 a = g_stats[r][0];
    for (int i = 1; i < nt; ++i) {
        float2 o = g_stats[r][i];
        comb(a.x, a.y, o.x, o.y);
    }
    float2 out; out.x = a.x; out.y = 1.0f / a.y;
    g_rowstats[r] = out;
}

// ---------------------------------------------------------------------------
// emb: softmax(scratch) @ ys_c, K = nc_pad (runtime). Producers apply exp;
// bx==0 producers scatter normalized weights to wout via g_idx.
// ---------------------------------------------------------------------------
__global__ __launch_bounds__(384, 1)
void emb_tc_kernel(float* __restrict__ emb, float* __restrict__ wout)
{
    extern __shared__ char smem[];
    const unsigned sb = smem_u32(smem);
    const int t = threadIdx.x;
    const int wid = t >> 5;
    const int lane = t & 31;
    const int b = blockIdx.z;
    const int rowBase = blockIdx.y * 128;   // x
    const int colBase = blockIdx.x * 128;   // d

    const int cnt = g_cnt[b];
    const int ncp = (cnt + 127) & ~127;
    const int nch = ncp >> 5;               // K chunks (>=4, <=32)

    const float* A   = g_scratch + (size_t)b * XL * YL + (size_t)rowBase * YL;
    const float* Byb = g_ys_c + (size_t)b * YL * DD + colBase;

    if (wid >= 8) {
        // ---------------- producer warps ----------------
        const int pt = t - 256;   // 0..127
        const bool wb = (blockIdx.x == 0);
        int* idxs = (int*)(smem + E_OFF_IDX);
        if (wb) {
            for (int q = pt; q < cnt; q += 128) idxs[q] = g_idx[b][q];
            bar_sync_n(8, 128);
        }

        int lr[8], lc4[8];
        unsigned loff[8];
#pragma unroll
        for (int i = 0; i < 8; ++i) {
            int s = pt + i * 128;
            lr[i]  = s >> 3;
            lc4[i] = s & 7;
            loff[i] = (unsigned)lr[i] * 128u +
                      (((unsigned)lc4[i] * 16u) ^ (((unsigned)(lr[i] & 7)) << 4));
        }
        float2 rs[8];
#pragma unroll
        for (int i = 0; i < 8; ++i)
            rs[i] = g_rowstats[b * XL + rowBase + lr[i]];

        // B transpose-gather: thread owns d-col pt; 8 float4 of k values.
        unsigned tboff[8];
#pragma unroll
        for (int q = 0; q < 8; ++q)
            tboff[q] = (unsigned)pt * 128u +
                       (((unsigned)(q * 16)) ^ (((unsigned)(pt & 7)) << 4));

        float* wrow = wout + (size_t)b * XL * YL;

        float4 pa[8], pb[8];
#pragma unroll
        for (int i = 0; i < 8; ++i)
            pa[i] = *reinterpret_cast<const float4*>(A + (size_t)lr[i] * YL + lc4[i] * 4);
        {
            const float* bp = Byb + pt;
#pragma unroll
            for (int q = 0; q < 8; ++q) {
                pb[q].x = bp[(size_t)(q * 4 + 0) * DD];
                pb[q].y = bp[(size_t)(q * 4 + 1) * DD];
                pb[q].z = bp[(size_t)(q * 4 + 2) * DD];
                pb[q].w = bp[(size_t)(q * 4 + 3) * DD];
            }
        }

        int s = 0;
        for (int c = 0; c < nch; ++c) {
            char* st = smem + s * E_STAGE;
            const int k0c = c * 32;
            if (c >= 3) bar_sync(4 + s);
#pragma unroll
            for (int i = 0; i < 8; ++i) {
                float4 e;
                e.x = __expf(pa[i].x - rs[i].x) * rs[i].y;
                e.y = __expf(pa[i].y - rs[i].x) * rs[i].y;
                e.z = __expf(pa[i].z - rs[i].x) * rs[i].y;
                e.w = __expf(pa[i].w - rs[i].x) * rs[i].y;
                float4 h, l;
                split4(e, h, l);
                *reinterpret_cast<float4*>(st + OFF_A_HI + loff[i]) = h;
                *reinterpret_cast<float4*>(st + OFF_A_LO + loff[i]) = l;
                if (wb) {
                    const int cbase = k0c + lc4[i] * 4;
                    float* wr = wrow + (size_t)(rowBase + lr[i]) * YL;
                    if (cbase + 0 < cnt) wr[idxs[cbase + 0]] = e.x;
                    if (cbase + 1 < cnt) wr[idxs[cbase + 1]] = e.y;
                    if (cbase + 2 < cnt) wr[idxs[cbase + 2]] = e.z;
                    if (cbase + 3 < cnt) wr[idxs[cbase + 3]] = e.w;
                }
            }
#pragma unroll
            for (int q = 0; q < 8; ++q) {
                *reinterpret_cast<float4*>(st + OFF_B_HI + tboff[q]) = hi4(pb[q]);
            }
            __threadfence_block();
            bar_arrive(1 + s);
            if (c < nch - 1) {
                const int k0 = (c + 1) * 32;
#pragma unroll
                for (int i = 0; i < 8; ++i)
                    pa[i] = *reinterpret_cast<const float4*>(A + (size_t)lr[i] * YL + k0 + lc4[i] * 4);
                const float* bp = Byb + (size_t)k0 * DD + pt;
#pragma unroll
                for (int q = 0; q < 8; ++q) {
                    pb[q].x = bp[(size_t)(q * 4 + 0) * DD];
                    pb[q].y = bp[(size_t)(q * 4 + 1) * DD];
                    pb[q].z = bp[(size_t)(q * 4 + 2) * DD];
                    pb[q].w = bp[(size_t)(q * 4 + 3) * DD];
                }
            }
            s = (s == 2) ? 0 : s + 1;
        }
        return;
    }

    // ---------------- consumer warps ----------------
    const int m0 = (wid & 1) * 64;
    const int n0 = (wid >> 1) * 32;

    const unsigned xr = (unsigned)(lane & 7) << 4;
    const unsigned rA = (unsigned)((lane & 7) + ((lane >> 3) & 1) * 8);
    const unsigned cA = (unsigned)((lane >> 4) << 4);
    const unsigned rB = (unsigned)((lane & 7) + ((lane >> 4) & 1) * 8);
    const unsigned cB = (unsigned)(((lane >> 3) & 1) << 4);
    const unsigned aRow = ((unsigned)m0 + rA) * 128u;
    const unsigned bRow = ((unsigned)n0 + rB) * 128u;
    unsigned colA[4], colB[4];
#pragma unroll
    for (int k8 = 0; k8 < 4; ++k8) {
        colA[k8] = ((unsigned)(k8 * 32) + cA) ^ xr;
        colB[k8] = ((unsigned)(k8 * 32) + cB) ^ xr;
    }

    float acc[4][4][4];
#pragma unroll
    for (int i = 0; i < 4; ++i)
#pragma unroll
        for (int j = 0; j < 4; ++j)
#pragma unroll
            for (int d = 0; d < 4; ++d) acc[i][j][d] = 0.0f;

    int s = 0;
    for (int c = 0; c < nch; ++c) {
        bar_sync(1 + s);
        mma_chunk2(sb + (unsigned)s * E_STAGE, aRow, bRow, colA, colB, acc);
        bar_arrive(4 + s);
        s = (s == 2) ? 0 : s + 1;
    }

    float* obase = emb + (size_t)b * XL * DD + colBase;
    const int g = lane >> 2;
    const int cp = (lane & 3) * 2;
#pragma unroll
    for (int i = 0; i < 4; ++i) {
        const int row = rowBase + m0 + 16 * i + g;
#pragma unroll
        for (int j = 0; j < 4; ++j) {
            const int col = n0 + 8 * j + cp;
            float2 v;
            v.x = acc[i][j][0];
            v.y = acc[i][j][1];
            *reinterpret_cast<float2*>(obase + (size_t)row * DD + col) = v;
            v.x = acc[i][j][2];
            v.y = acc[i][j][3];
            *reinterpret_cast<float2*>(obase + (size_t)(row + 8) * DD + col) = v;
        }
    }
}

// ---------------------------------------------------------------------------
extern "C" void kernel_launch(void* const* d_in, const int* in_sizes, int n_in,
                              void* d_out, int out_size)
{
    const float* xs   = (const float*)d_in[0];
    const float* ys   = (const float*)d_in[1];
    const int*   mask = (const int*)d_in[2];

    float* emb = (float*)d_out;                           // [B, XL, D]
    float* w   = (float*)d_out + (size_t)BB * XL * DD;    // [B, XL, YL]

    cudaFuncSetAttribute(scores_tc_kernel,
                         cudaFuncAttributeMaxDynamicSharedMemorySize, S_SMEM_BYTES);
    cudaFuncSetAttribute(emb_tc_kernel,
                         cudaFuncAttributeMaxDynamicSharedMemorySize, E_SMEM_BYTES);

    compact_kernel<<<BB, 1024>>>(mask);
    gather_kernel<<<dim3(64, BB), 256>>>(ys);
    zerofill_kernel<<<(BB * XL * (YL / 16)) / 256, 256>>>(w);
    scores_tc_kernel<<<dim3(8, 8, BB), 384, S_SMEM_BYTES>>>(xs);
    reduce_stats_kernel<<<(BB * XL) / 256, 256>>>();
    emb_tc_kernel<<<dim3(8, 8, BB), 384, E_SMEM_BYTES>>>(emb, w);
}

// round 16
// speedup vs baseline: 1.5282x; 1.0511x over previous
#include <cuda_runtime.h>

// Shapes fixed by the problem
#define BB 16
#define XL 1024
#define YL 1024
#define DD 1024
#define NEG_INF (-1e20f)

// ---------------------------------------------------------------------------
// Mask-compacted attention (R15 structure).
//  compact -> gather -> zerofill -> scores(3-product, compacted N) ->
//  reduce -> emb(SINGLE-product, K = nc_pad).
// emb error model: dropped w_lo*y and w_hi*y_lo terms are each ~2^-12 rel;
// quadrature with measured 2.09e-4 baseline -> ~3.2e-4, under 1e-3.
// GEMM config: 384 thr = 8 consumer warps (64x32 tiles) + 4 producer warps,
// 3-stage SW128 K-major smem ring.
// ---------------------------------------------------------------------------
#define OFF_A_HI 0
#define OFF_A_LO 16384
#define OFF_B_HI 32768
#define OFF_B_LO 49152
#define S_STAGE 65536
#define S_OFF_STATS (3 * S_STAGE)              // 128 rows x 4 float2 = 4KB
#define S_SMEM_BYTES (S_OFF_STATS + 4096)

// emb stage: {A_HI, B_HI} only
#define E_OFF_B 16384
#define E_STAGE 32768
#define E_OFF_IDX (3 * E_STAGE)                // 1024 ints = 4KB
#define E_SMEM_BYTES (E_OFF_IDX + 4096)

#define NBAR_THREADS 384

// Device-global scratch (sanctioned path; no allocations)
__device__ float  g_scratch[(size_t)BB * XL * YL];   // raw compacted scores
__device__ float  g_ys_c[(size_t)BB * YL * DD];      // compacted ys
__device__ int    g_idx[BB][YL];                     // compacted -> original y
__device__ int    g_cnt[BB];                         // unmasked count per batch
__device__ float2 g_stats[BB * XL][8];               // per-tile (m, sumexp)
__device__ float2 g_rowstats[BB * XL];               // per-row (m, 1/sum)

// ---------------------------------------------------------------------------
// Helpers
// ---------------------------------------------------------------------------
static __device__ __forceinline__ unsigned smem_u32(const void* p) {
    unsigned a;
    asm("{ .reg .u64 t; cvta.to.shared.u64 t, %1; cvt.u32.u64 %0, t; }"
        : "=r"(a) : "l"(p));
    return a;
}
static __device__ __forceinline__ float tf32_rna(float x) {
    unsigned u;
    asm("cvt.rna.tf32.f32 %0, %1;" : "=r"(u) : "f"(x));
    return __uint_as_float(u);
}
static __device__ __forceinline__ void split4(float4 v, float4& h, float4& l) {
    h.x = tf32_rna(v.x); l.x = tf32_rna(v.x - h.x);
    h.y = tf32_rna(v.y); l.y = tf32_rna(v.y - h.y);
    h.z = tf32_rna(v.z); l.z = tf32_rna(v.z - h.z);
    h.w = tf32_rna(v.w); l.w = tf32_rna(v.w - h.w);
}
static __device__ __forceinline__ float4 hi4(float4 v) {
    float4 h;
    h.x = tf32_rna(v.x); h.y = tf32_rna(v.y);
    h.z = tf32_rna(v.z); h.w = tf32_rna(v.w);
    return h;
}
static __device__ __forceinline__ void bar_sync(int id) {
    asm volatile("bar.sync %0, %1;" :: "r"(id), "n"(NBAR_THREADS) : "memory");
}
static __device__ __forceinline__ void bar_arrive(int id) {
    asm volatile("bar.arrive %0, %1;" :: "r"(id), "n"(NBAR_THREADS) : "memory");
}
static __device__ __forceinline__ void bar_sync_n(int id, int n) {
    asm volatile("bar.sync %0, %1;" :: "r"(id), "r"(n) : "memory");
}

#define LDSM_X4(r, addr)                                                      \
    asm volatile(                                                             \
        "ldmatrix.sync.aligned.m8n8.x4.shared.b16 {%0,%1,%2,%3}, [%4];"       \
        : "=r"((r)[0]), "=r"((r)[1]), "=r"((r)[2]), "=r"((r)[3])              \
        : "r"(addr))

#define MMA_TF32(d, a, b0, b1)                                                \
    asm volatile(                                                             \
        "mma.sync.aligned.m16n8k8.row.col.f32.tf32.tf32.f32 "                 \
        "{%0,%1,%2,%3}, {%4,%5,%6,%7}, {%8,%9}, {%0,%1,%2,%3};"               \
        : "+f"((d)[0]), "+f"((d)[1]), "+f"((d)[2]), "+f"((d)[3])              \
        : "r"((a)[0]), "r"((a)[1]), "r"((a)[2]), "r"((a)[3]),                 \
          "r"(b0), "r"(b1))

// ---------------------------------------------------------------------------
// scores consumer MMA: 3 products (hh, lh, hl). 8 warps, warp tile 64x32.
// ---------------------------------------------------------------------------
static __device__ __forceinline__ void mma_chunk3(
    unsigned base, unsigned aRow, unsigned bRow,
    const unsigned colA[4], const unsigned colB[4], float acc[4][4][4])
{
    unsigned fa[4][4], fb[2][4], fc[4][4];
#pragma unroll
    for (int k8 = 0; k8 < 4; ++k8) {
#pragma unroll
        for (int i = 0; i < 4; ++i)
            LDSM_X4(fa[i], base + OFF_A_HI + aRow + 2048u * i + colA[k8]);
#pragma unroll
        for (int jp = 0; jp < 2; ++jp)
            LDSM_X4(fb[jp], base + OFF_B_HI + bRow + 2048u * jp + colB[k8]);
#pragma unroll
        for (int i = 0; i < 4; ++i)
            LDSM_X4(fc[i], base + OFF_A_LO + aRow + 2048u * i + colA[k8]);

        // hi*hi
#pragma unroll
        for (int i = 0; i < 4; ++i)
#pragma unroll
            for (int j = 0; j < 4; ++j)
                MMA_TF32(acc[i][j], fa[i], fb[j >> 1][(j & 1) * 2],
                         fb[j >> 1][(j & 1) * 2 + 1]);
        // lo*hi
#pragma unroll
        for (int i = 0; i < 4; ++i)
#pragma unroll
            for (int j = 0; j < 4; ++j)
                MMA_TF32(acc[i][j], fc[i], fb[j >> 1][(j & 1) * 2],
                         fb[j >> 1][(j & 1) * 2 + 1]);
        // hi*lo
#pragma unroll
        for (int jp = 0; jp < 2; ++jp)
            LDSM_X4(fc[jp], base + OFF_B_LO + bRow + 2048u * jp + colB[k8]);
#pragma unroll
        for (int i = 0; i < 4; ++i)
#pragma unroll
            for (int j = 0; j < 4; ++j)
                MMA_TF32(acc[i][j], fa[i], fc[j >> 1][(j & 1) * 2],
                         fc[j >> 1][(j & 1) * 2 + 1]);
    }
}

// emb consumer MMA: single product (hh). Stage = {A_HI at 0, B_HI at E_OFF_B}.
static __device__ __forceinline__ void mma_chunk1(
    unsigned base, unsigned aRow, unsigned bRow,
    const unsigned colA[4], const unsigned colB[4], float acc[4][4][4])
{
    unsigned fa[4][4], fb[2][4];
#pragma unroll
    for (int k8 = 0; k8 < 4; ++k8) {
#pragma unroll
        for (int i = 0; i < 4; ++i)
            LDSM_X4(fa[i], base + aRow + 2048u * i + colA[k8]);
#pragma unroll
        for (int jp = 0; jp < 2; ++jp)
            LDSM_X4(fb[jp], base + E_OFF_B + bRow + 2048u * jp + colB[k8]);

#pragma unroll
        for (int i = 0; i < 4; ++i)
#pragma unroll
            for (int j = 0; j < 4; ++j)
                MMA_TF32(acc[i][j], fa[i], fb[j >> 1][(j & 1) * 2],
                         fb[j >> 1][(j & 1) * 2 + 1]);
    }
}

// online-softmax pair combine
static __device__ __forceinline__ void comb(float& m, float& s, float mo, float so) {
    float mn = fmaxf(m, mo);
    s = s * __expf(m - mn) + so * __expf(mo - mn);
    m = mn;
}

// ---------------------------------------------------------------------------
// compact: one block per batch; inclusive scan of mask -> idx list + count
// ---------------------------------------------------------------------------
__global__ __launch_bounds__(1024)
void compact_kernel(const int* __restrict__ mask)
{
    __shared__ int s[1024];
    const int b = blockIdx.x;
    const int t = threadIdx.x;
    const int mk = mask[b * YL + t];
    s[t] = mk;
    __syncthreads();
#pragma unroll
    for (int off = 1; off < 1024; off <<= 1) {
        int v = (t >= off) ? s[t - off] : 0;
        __syncthreads();
        s[t] += v;
        __syncthreads();
    }
    if (mk) g_idx[b][s[t] - 1] = t;
    if (t == 1023) g_cnt[b] = s[1023];
}

// ---------------------------------------------------------------------------
// gather: g_ys_c[b][j][:] = ys[b][idx[j]][:]; zero rows [cnt, nc_pad)
// ---------------------------------------------------------------------------
__global__ __launch_bounds__(256)
void gather_kernel(const float* __restrict__ ys)
{
    const int b = blockIdx.y;
    const int t = threadIdx.x;
    const int cnt = g_cnt[b];
    const int ncp = (cnt + 127) & ~127;
    for (int r = 0; r < 16; ++r) {
        const int j = blockIdx.x * 16 + r;
        if (j >= ncp) break;
        float4 v = make_float4(0.f, 0.f, 0.f, 0.f);
        if (j < cnt) {
            const int y = g_idx[b][j];
            v = *reinterpret_cast<const float4*>(ys + ((size_t)b * YL + y) * DD + t * 4);
        }
        *reinterpret_cast<float4*>(g_ys_c + ((size_t)b * YL + j) * DD + t * 4) = v;
    }
}

// ---------------------------------------------------------------------------
// zerofill: weight output region -> 0
// ---------------------------------------------------------------------------
__global__ __launch_bounds__(256)
void zerofill_kernel(float* __restrict__ w)
{
    const size_t i = ((size_t)blockIdx.x * 256 + threadIdx.x) * 16;
    float4 z = make_float4(0.f, 0.f, 0.f, 0.f);
#pragma unroll
    for (int q = 0; q < 4; ++q)
        *reinterpret_cast<float4*>(w + i + q * 4) = z;
}

// ---------------------------------------------------------------------------
// scores: xs @ ys_c^T; raw scores -> g_scratch; per-tile stats -> g_stats
// ---------------------------------------------------------------------------
__global__ __launch_bounds__(384, 1)
void scores_tc_kernel(const float* __restrict__ xs)
{
    extern __shared__ char smem[];
    const unsigned sb = smem_u32(smem);
    const int t = threadIdx.x;
    const int wid = t >> 5;
    const int lane = t & 31;
    const int b = blockIdx.z;
    const int rowBase = blockIdx.y * 128;
    const int colBase = blockIdx.x * 128;

    const int cnt = g_cnt[b];
    const int ncp = (cnt + 127) & ~127;
    if (colBase >= ncp) return;            // uniform early exit, no barriers yet

    const float* A  = xs + (size_t)b * XL * DD + (size_t)rowBase * DD;
    const float* Bp = g_ys_c + (size_t)b * YL * DD + (size_t)colBase * DD;

    if (wid >= 8) {
        // ---------------- producer warps (8..11) ----------------
        const int pt = t - 256;   // 0..127

        int lr[8], lc4[8];
        unsigned loff[8];
#pragma unroll
        for (int i = 0; i < 8; ++i) {
            int s = pt + i * 128;
            lr[i]  = s >> 3;
            lc4[i] = s & 7;
            loff[i] = (unsigned)lr[i] * 128u +
                      (((unsigned)lc4[i] * 16u) ^ (((unsigned)(lr[i] & 7)) << 4));
        }

        float4 pa[8], pb[8];
#pragma unroll
        for (int i = 0; i < 8; ++i) {
            pa[i] = *reinterpret_cast<const float4*>(A  + (size_t)lr[i] * DD + lc4[i] * 4);
            pb[i] = *reinterpret_cast<const float4*>(Bp + (size_t)lr[i] * DD + lc4[i] * 4);
        }

        int s = 0;
        for (int c = 0; c < 32; ++c) {
            char* st = smem + s * S_STAGE;
            if (c >= 3) bar_sync(4 + s);
#pragma unroll
            for (int i = 0; i < 8; ++i) {
                float4 h, l;
                split4(pa[i], h, l);
                *reinterpret_cast<float4*>(st + OFF_A_HI + loff[i]) = h;
                *reinterpret_cast<float4*>(st + OFF_A_LO + loff[i]) = l;
                split4(pb[i], h, l);
                *reinterpret_cast<float4*>(st + OFF_B_HI + loff[i]) = h;
                *reinterpret_cast<float4*>(st + OFF_B_LO + loff[i]) = l;
            }
            __threadfence_block();
            bar_arrive(1 + s);
            if (c < 31) {
                const int k0 = (c + 1) * 32;
#pragma unroll
                for (int i = 0; i < 8; ++i) {
                    pa[i] = *reinterpret_cast<const float4*>(A  + (size_t)lr[i] * DD + k0 + lc4[i] * 4);
                    pb[i] = *reinterpret_cast<const float4*>(Bp + (size_t)lr[i] * DD + k0 + lc4[i] * 4);
                }
            }
            s = (s == 2) ? 0 : s + 1;
        }
        return;
    }

    // ---------------- consumer warps (0..7) ----------------
    const int m0 = (wid & 1) * 64;
    const int n0 = (wid >> 1) * 32;

    const unsigned xr = (unsigned)(lane & 7) << 4;
    const unsigned rA = (unsigned)((lane & 7) + ((lane >> 3) & 1) * 8);
    const unsigned cA = (unsigned)((lane >> 4) << 4);
    const unsigned rB = (unsigned)((lane & 7) + ((lane >> 4) & 1) * 8);
    const unsigned cB = (unsigned)(((lane >> 3) & 1) << 4);
    const unsigned aRow = ((unsigned)m0 + rA) * 128u;
    const unsigned bRow = ((unsigned)n0 + rB) * 128u;
    unsigned colA[4], colB[4];
#pragma unroll
    for (int k8 = 0; k8 < 4; ++k8) {
        colA[k8] = ((unsigned)(k8 * 32) + cA) ^ xr;
        colB[k8] = ((unsigned)(k8 * 32) + cB) ^ xr;
    }

    float acc[4][4][4];
#pragma unroll
    for (int i = 0; i < 4; ++i)
#pragma unroll
        for (int j = 0; j < 4; ++j)
#pragma unroll
            for (int d = 0; d < 4; ++d) acc[i][j][d] = 0.0f;

    int s = 0;
    for (int c = 0; c < 32; ++c) {
        bar_sync(1 + s);
        mma_chunk3(sb + (unsigned)s * S_STAGE, aRow, bRow, colA, colB, acc);
        bar_arrive(4 + s);
        s = (s == 2) ? 0 : s + 1;
    }

    // epilogue: raw scores -> scratch (NEG_INF beyond cnt); per-row stats
    float2* stat = (float2*)(smem + S_OFF_STATS);   // [128][4]
    float* sc = g_scratch + (size_t)b * XL * YL + (size_t)rowBase * YL + colBase;
    const int g = lane >> 2;
    const int cp = (lane & 3) * 2;
    const int nwid = wid >> 1;
    const int lim = cnt - colBase;                  // valid cols in this tile

#pragma unroll
    for (int i = 0; i < 4; ++i) {
        const int rowL = m0 + 16 * i + g;
        float mL = NEG_INF, mH = NEG_INF;
        float sL = 0.0f, sH = 0.0f;
        float v0s[4], v1s[4], v2s[4], v3s[4];
#pragma unroll
        for (int j = 0; j < 4; ++j) {
            const int col = n0 + 8 * j + cp;
            const bool ok0 = col < lim;
            const bool ok1 = (col + 1) < lim;
            float v0 = ok0 ? acc[i][j][0] : NEG_INF;
            float v1 = ok1 ? acc[i][j][1] : NEG_INF;
            float v2 = ok0 ? acc[i][j][2] : NEG_INF;
            float v3 = ok1 ? acc[i][j][3] : NEG_INF;
            v0s[j] = v0; v1s[j] = v1; v2s[j] = v2; v3s[j] = v3;
            float2 w0; w0.x = v0; w0.y = v1;
            float2 w1; w1.x = v2; w1.y = v3;
            *reinterpret_cast<float2*>(sc + (size_t)rowL * YL + col) = w0;
            *reinterpret_cast<float2*>(sc + (size_t)(rowL + 8) * YL + col) = w1;
            mL = fmaxf(mL, fmaxf(v0, v1));
            mH = fmaxf(mH, fmaxf(v2, v3));
        }
#pragma unroll
        for (int j = 0; j < 4; ++j) {
            sL += __expf(v0s[j] - mL) + __expf(v1s[j] - mL);
            sH += __expf(v2s[j] - mH) + __expf(v3s[j] - mH);
        }
        // reduce across the 4 lanes sharing each row
#pragma unroll
        for (int d = 1; d < 4; d <<= 1) {
            float mo = __shfl_xor_sync(0xFFFFFFFFu, mL, d);
            float so = __shfl_xor_sync(0xFFFFFFFFu, sL, d);
            comb(mL, sL, mo, so);
            mo = __shfl_xor_sync(0xFFFFFFFFu, mH, d);
            so = __shfl_xor_sync(0xFFFFFFFFu, sH, d);
            comb(mH, sH, mo, so);
        }
        if ((lane & 3) == 0) {
            float2 v; v.x = mL; v.y = sL;
            stat[rowL * 4 + nwid] = v;
            v.x = mH; v.y = sH;
            stat[(rowL + 8) * 4 + nwid] = v;
        }
    }
    bar_sync_n(7, 256);                // consumer warps only
    if (t < 128) {
        float2 a = stat[t * 4 + 0];
#pragma unroll
        for (int q = 1; q < 4; ++q) {
            float2 o = stat[t * 4 + q];
            comb(a.x, a.y, o.x, o.y);
        }
        g_stats[b * XL + rowBase + t][blockIdx.x] = a;
    }
}

// ---------------------------------------------------------------------------
// reduce: fold active per-tile stats into per-row (max, 1/sum)
// ---------------------------------------------------------------------------
__global__ __launch_bounds__(256)
void reduce_stats_kernel()
{
    const int r = blockIdx.x * 256 + threadIdx.x;
    const int b = r >> 10;
    const int nt = (g_cnt[b] + 127) >> 7;
    float2 a = g_stats[r][0];
    for (int i = 1; i < nt; ++i) {
        float2 o = g_stats[r][i];
        comb(a.x, a.y, o.x, o.y);
    }
    float2 out; out.x = a.x; out.y = 1.0f / a.y;
    g_rowstats[r] = out;
}

// ---------------------------------------------------------------------------
// emb: softmax(scratch) @ ys_c, K = nc_pad (runtime), SINGLE MMA product.
// Producers apply exp; bx==0 producers scatter weights to wout via g_idx.
// ---------------------------------------------------------------------------
__global__ __launch_bounds__(384, 1)
void emb_tc_kernel(float* __restrict__ emb, float* __restrict__ wout)
{
    extern __shared__ char smem[];
    const unsigned sb = smem_u32(smem);
    const int t = threadIdx.x;
    const int wid = t >> 5;
    const int lane = t & 31;
    const int b = blockIdx.z;
    const int rowBase = blockIdx.y * 128;   // x
    const int colBase = blockIdx.x * 128;   // d

    const int cnt = g_cnt[b];
    const int ncp = (cnt + 127) & ~127;
    const int nch = ncp >> 5;               // K chunks

    const float* A   = g_scratch + (size_t)b * XL * YL + (size_t)rowBase * YL;
    const float* Byb = g_ys_c + (size_t)b * YL * DD + colBase;

    if (wid >= 8) {
        // ---------------- producer warps ----------------
        const int pt = t - 256;   // 0..127
        const bool wb = (blockIdx.x == 0);
        int* idxs = (int*)(smem + E_OFF_IDX);
        if (wb) {
            for (int q = pt; q < cnt; q += 128) idxs[q] = g_idx[b][q];
            bar_sync_n(8, 128);
        }

        int lr[8], lc4[8];
        unsigned loff[8];
#pragma unroll
        for (int i = 0; i < 8; ++i) {
            int s = pt + i * 128;
            lr[i]  = s >> 3;
            lc4[i] = s & 7;
            loff[i] = (unsigned)lr[i] * 128u +
                      (((unsigned)lc4[i] * 16u) ^ (((unsigned)(lr[i] & 7)) << 4));
        }
        float2 rs[8];
#pragma unroll
        for (int i = 0; i < 8; ++i)
            rs[i] = g_rowstats[b * XL + rowBase + lr[i]];

        // B transpose-gather: thread owns d-col pt; 8 float4 of k values.
        unsigned tboff[8];
#pragma unroll
        for (int q = 0; q < 8; ++q)
            tboff[q] = (unsigned)pt * 128u +
                       (((unsigned)(q * 16)) ^ (((unsigned)(pt & 7)) << 4));

        float* wrow = wout + (size_t)b * XL * YL;

        float4 pa[8], pb[8];
#pragma unroll
        for (int i = 0; i < 8; ++i)
            pa[i] = *reinterpret_cast<const float4*>(A + (size_t)lr[i] * YL + lc4[i] * 4);
        {
            const float* bp = Byb + pt;
#pragma unroll
            for (int q = 0; q < 8; ++q) {
                pb[q].x = bp[(size_t)(q * 4 + 0) * DD];
                pb[q].y = bp[(size_t)(q * 4 + 1) * DD];
                pb[q].z = bp[(size_t)(q * 4 + 2) * DD];
                pb[q].w = bp[(size_t)(q * 4 + 3) * DD];
            }
        }

        int s = 0;
        for (int c = 0; c < nch; ++c) {
            char* st = smem + s * E_STAGE;
            const int k0c = c * 32;
            if (c >= 3) bar_sync(4 + s);
#pragma unroll
            for (int i = 0; i < 8; ++i) {
                float4 e;
                e.x = __expf(pa[i].x - rs[i].x) * rs[i].y;
                e.y = __expf(pa[i].y - rs[i].x) * rs[i].y;
                e.z = __expf(pa[i].z - rs[i].x) * rs[i].y;
                e.w = __expf(pa[i].w - rs[i].x) * rs[i].y;
                *reinterpret_cast<float4*>(st + loff[i]) = hi4(e);
                if (wb) {
                    const int cbase = k0c + lc4[i] * 4;
                    float* wr = wrow + (size_t)(rowBase + lr[i]) * YL;
                    if (cbase + 0 < cnt) wr[idxs[cbase + 0]] = e.x;
                    if (cbase + 1 < cnt) wr[idxs[cbase + 1]] = e.y;
                    if (cbase + 2 < cnt) wr[idxs[cbase + 2]] = e.z;
                    if (cbase + 3 < cnt) wr[idxs[cbase + 3]] = e.w;
                }
            }
#pragma unroll
            for (int q = 0; q < 8; ++q) {
                *reinterpret_cast<float4*>(st + E_OFF_B + tboff[q]) = hi4(pb[q]);
            }
            __threadfence_block();
            bar_arrive(1 + s);
            if (c < nch - 1) {
                const int k0 = (c + 1) * 32;
#pragma unroll
                for (int i = 0; i < 8; ++i)
                    pa[i] = *reinterpret_cast<const float4*>(A + (size_t)lr[i] * YL + k0 + lc4[i] * 4);
                const float* bp = Byb + (size_t)k0 * DD + pt;
#pragma unroll
                for (int q = 0; q < 8; ++q) {
                    pb[q].x = bp[(size_t)(q * 4 + 0) * DD];
                    pb[q].y = bp[(size_t)(q * 4 + 1) * DD];
                    pb[q].z = bp[(size_t)(q * 4 + 2) * DD];
                    pb[q].w = bp[(size_t)(q * 4 + 3) * DD];
                }
            }
            s = (s == 2) ? 0 : s + 1;
        }
        return;
    }

    // ---------------- consumer warps ----------------
    const int m0 = (wid & 1) * 64;
    const int n0 = (wid >> 1) * 32;

    const unsigned xr = (unsigned)(lane & 7) << 4;
    const unsigned rA = (unsigned)((lane & 7) + ((lane >> 3) & 1) * 8);
    const unsigned cA = (unsigned)((lane >> 4) << 4);
    const unsigned rB = (unsigned)((lane & 7) + ((lane >> 4) & 1) * 8);
    const unsigned cB = (unsigned)(((lane >> 3) & 1) << 4);
    const unsigned aRow = ((unsigned)m0 + rA) * 128u;
    const unsigned bRow = ((unsigned)n0 + rB) * 128u;
    unsigned colA[4], colB[4];
#pragma unroll
    for (int k8 = 0; k8 < 4; ++k8) {
        colA[k8] = ((unsigned)(k8 * 32) + cA) ^ xr;
        colB[k8] = ((unsigned)(k8 * 32) + cB) ^ xr;
    }

    float acc[4][4][4];
#pragma unroll
    for (int i = 0; i < 4; ++i)
#pragma unroll
        for (int j = 0; j < 4; ++j)
#pragma unroll
            for (int d = 0; d < 4; ++d) acc[i][j][d] = 0.0f;

    int s = 0;
    for (int c = 0; c < nch; ++c) {
        bar_sync(1 + s);
        mma_chunk1(sb + (unsigned)s * E_STAGE, aRow, bRow, colA, colB, acc);
        bar_arrive(4 + s);
        s = (s == 2) ? 0 : s + 1;
    }

    float* obase = emb + (size_t)b * XL * DD + colBase;
    const int g = lane >> 2;
    const int cp = (lane & 3) * 2;
#pragma unroll
    for (int i = 0; i < 4; ++i) {
        const int row = rowBase + m0 + 16 * i + g;
#pragma unroll
        for (int j = 0; j < 4; ++j) {
            const int col = n0 + 8 * j + cp;
            float2 v;
            v.x = acc[i][j][0];
            v.y = acc[i][j][1];
            *reinterpret_cast<float2*>(obase + (size_t)row * DD + col) = v;
            v.x = acc[i][j][2];
            v.y = acc[i][j][3];
            *reinterpret_cast<float2*>(obase + (size_t)(row + 8) * DD + col) = v;
        }
    }
}

// ---------------------------------------------------------------------------
extern "C" void kernel_launch(void* const* d_in, const int* in_sizes, int n_in,
                              void* d_out, int out_size)
{
    const float* xs   = (const float*)d_in[0];
    const float* ys   = (const float*)d_in[1];
    const int*   mask = (const int*)d_in[2];

    float* emb = (float*)d_out;                           // [B, XL, D]
    float* w   = (float*)d_out + (size_t)BB * XL * DD;    // [B, XL, YL]

    cudaFuncSetAttribute(scores_tc_kernel,
                         cudaFuncAttributeMaxDynamicSharedMemorySize, S_SMEM_BYTES);
    cudaFuncSetAttribute(emb_tc_kernel,
                         cudaFuncAttributeMaxDynamicSharedMemorySize, E_SMEM_BYTES);

    compact_kernel<<<BB, 1024>>>(mask);
    gather_kernel<<<dim3(64, BB), 256>>>(ys);
    zerofill_kernel<<<(BB * XL * (YL / 16)) / 256, 256>>>(w);
    scores_tc_kernel<<<dim3(8, 8, BB), 384, S_SMEM_BYTES>>>(xs);
    reduce_stats_kernel<<<(BB * XL) / 256, 256>>>();
    emb_tc_kernel<<<dim3(8, 8, BB), 384, E_SMEM_BYTES>>>(emb, w);
}

// round 17
// speedup vs baseline: 1.7353x; 1.1356x over previous
#include <cuda_runtime.h>
#include <cuda_bf16.h>

// Shapes fixed by the problem
#define BB 16
#define XL 1024
#define YL 1024
#define DD 1024
#define NEG_INF (-1e20f)

// ---------------------------------------------------------------------------
// Mask-compacted attention.
//  compact -> gather -> zerofill -> scores(BF16 3-product, compacted N) ->
//  reduce -> emb(TF32 single-product, K = nc_pad).
// scores now uses bf16 hi/lo split with mma.m16n8k16: K-chunk=64 (128B rows),
// same SW128 layout and ldmatrix lane geometry as the tf32 path.
// GEMM config: 384 thr = 8 consumer warps (64x32 tiles) + 4 producer warps,
// 3-stage SW128 K-major smem ring.
// ---------------------------------------------------------------------------
#define OFF_A_HI 0
#define OFF_A_LO 16384
#define OFF_B_HI 32768
#define OFF_B_LO 49152
#define S_STAGE 65536
#define S_OFF_STATS (3 * S_STAGE)              // 128 rows x 4 float2 = 4KB
#define S_SMEM_BYTES (S_OFF_STATS + 4096)

// emb stage: {A_HI, B_HI} only (tf32)
#define E_OFF_B 16384
#define E_STAGE 32768
#define E_OFF_IDX (3 * E_STAGE)                // 1024 ints = 4KB
#define E_SMEM_BYTES (E_OFF_IDX + 4096)

#define NBAR_THREADS 384

// Device-global scratch (sanctioned path; no allocations)
__device__ float  g_scratch[(size_t)BB * XL * YL];   // raw compacted scores
__device__ float  g_ys_c[(size_t)BB * YL * DD];      // compacted ys
__device__ int    g_idx[BB][YL];                     // compacted -> original y
__device__ int    g_cnt[BB];                         // unmasked count per batch
__device__ float2 g_stats[BB * XL][8];               // per-tile (m, sumexp)
__device__ float2 g_rowstats[BB * XL];               // per-row (m, 1/sum)

// ---------------------------------------------------------------------------
// Helpers
// ---------------------------------------------------------------------------
static __device__ __forceinline__ unsigned smem_u32(const void* p) {
    unsigned a;
    asm("{ .reg .u64 t; cvta.to.shared.u64 t, %1; cvt.u32.u64 %0, t; }"
        : "=r"(a) : "l"(p));
    return a;
}
static __device__ __forceinline__ float tf32_rna(float x) {
    unsigned u;
    asm("cvt.rna.tf32.f32 %0, %1;" : "=r"(u) : "f"(x));
    return __uint_as_float(u);
}
static __device__ __forceinline__ float4 hi4(float4 v) {
    float4 h;
    h.x = tf32_rna(v.x); h.y = tf32_rna(v.y);
    h.z = tf32_rna(v.z); h.w = tf32_rna(v.w);
    return h;
}
static __device__ __forceinline__ unsigned pack_bf2(__nv_bfloat16 a, __nv_bfloat16 b) {
    return ((unsigned)__bfloat16_as_ushort(b) << 16) | (unsigned)__bfloat16_as_ushort(a);
}
// split float4 into bf16 hi (8B) and bf16 lo (8B)
static __device__ __forceinline__ void split4_bf(float4 v, uint2& h, uint2& l) {
    __nv_bfloat16 hx = __float2bfloat16(v.x);
    __nv_bfloat16 hy = __float2bfloat16(v.y);
    __nv_bfloat16 hz = __float2bfloat16(v.z);
    __nv_bfloat16 hw = __float2bfloat16(v.w);
    __nv_bfloat16 lx = __float2bfloat16(v.x - __bfloat162float(hx));
    __nv_bfloat16 ly = __float2bfloat16(v.y - __bfloat162float(hy));
    __nv_bfloat16 lz = __float2bfloat16(v.z - __bfloat162float(hz));
    __nv_bfloat16 lw = __float2bfloat16(v.w - __bfloat162float(hw));
    h.x = pack_bf2(hx, hy); h.y = pack_bf2(hz, hw);
    l.x = pack_bf2(lx, ly); l.y = pack_bf2(lz, lw);
}
static __device__ __forceinline__ void bar_sync(int id) {
    asm volatile("bar.sync %0, %1;" :: "r"(id), "n"(NBAR_THREADS) : "memory");
}
static __device__ __forceinline__ void bar_arrive(int id) {
    asm volatile("bar.arrive %0, %1;" :: "r"(id), "n"(NBAR_THREADS) : "memory");
}
static __device__ __forceinline__ void bar_sync_n(int id, int n) {
    asm volatile("bar.sync %0, %1;" :: "r"(id), "r"(n) : "memory");
}

#define LDSM_X4(r, addr)                                                      \
    asm volatile(                                                             \
        "ldmatrix.sync.aligned.m8n8.x4.shared.b16 {%0,%1,%2,%3}, [%4];"       \
        : "=r"((r)[0]), "=r"((r)[1]), "=r"((r)[2]), "=r"((r)[3])              \
        : "r"(addr))

#define MMA_TF32(d, a, b0, b1)                                                \
    asm volatile(                                                             \
        "mma.sync.aligned.m16n8k8.row.col.f32.tf32.tf32.f32 "                 \
        "{%0,%1,%2,%3}, {%4,%5,%6,%7}, {%8,%9}, {%0,%1,%2,%3};"               \
        : "+f"((d)[0]), "+f"((d)[1]), "+f"((d)[2]), "+f"((d)[3])              \
        : "r"((a)[0]), "r"((a)[1]), "r"((a)[2]), "r"((a)[3]),                 \
          "r"(b0), "r"(b1))

#define MMA_BF16(d, a, b0, b1)                                                \
    asm volatile(                                                             \
        "mma.sync.aligned.m16n8k16.row.col.f32.bf16.bf16.f32 "                \
        "{%0,%1,%2,%3}, {%4,%5,%6,%7}, {%8,%9}, {%0,%1,%2,%3};"               \
        : "+f"((d)[0]), "+f"((d)[1]), "+f"((d)[2]), "+f"((d)[3])              \
        : "r"((a)[0]), "r"((a)[1]), "r"((a)[2]), "r"((a)[3]),                 \
          "r"(b0), "r"(b1))

// ---------------------------------------------------------------------------
// scores consumer MMA (bf16): 3 products (hh, lh, hl). 8 warps, 64x32 tiles.
// K-chunk = 64 bf16 = 4 k16 steps of 32B; same address geometry as tf32 path.
// ---------------------------------------------------------------------------
static __device__ __forceinline__ void mma_chunk3(
    unsigned base, unsigned aRow, unsigned bRow,
    const unsigned colA[4], const unsigned colB[4], float acc[4][4][4])
{
    unsigned fa[4][4], fb[2][4], fc[4][4];
#pragma unroll
    for (int k16 = 0; k16 < 4; ++k16) {
#pragma unroll
        for (int i = 0; i < 4; ++i)
            LDSM_X4(fa[i], base + OFF_A_HI + aRow + 2048u * i + colA[k16]);
#pragma unroll
        for (int jp = 0; jp < 2; ++jp)
            LDSM_X4(fb[jp], base + OFF_B_HI + bRow + 2048u * jp + colB[k16]);
#pragma unroll
        for (int i = 0; i < 4; ++i)
            LDSM_X4(fc[i], base + OFF_A_LO + aRow + 2048u * i + colA[k16]);

        // hi*hi
#pragma unroll
        for (int i = 0; i < 4; ++i)
#pragma unroll
            for (int j = 0; j < 4; ++j)
                MMA_BF16(acc[i][j], fa[i], fb[j >> 1][(j & 1) * 2],
                         fb[j >> 1][(j & 1) * 2 + 1]);
        // lo*hi
#pragma unroll
        for (int i = 0; i < 4; ++i)
#pragma unroll
            for (int j = 0; j < 4; ++j)
                MMA_BF16(acc[i][j], fc[i], fb[j >> 1][(j & 1) * 2],
                         fb[j >> 1][(j & 1) * 2 + 1]);
        // hi*lo
#pragma unroll
        for (int jp = 0; jp < 2; ++jp)
            LDSM_X4(fc[jp], base + OFF_B_LO + bRow + 2048u * jp + colB[k16]);
#pragma unroll
        for (int i = 0; i < 4; ++i)
#pragma unroll
            for (int j = 0; j < 4; ++j)
                MMA_BF16(acc[i][j], fa[i], fc[j >> 1][(j & 1) * 2],
                         fc[j >> 1][(j & 1) * 2 + 1]);
    }
}

// emb consumer MMA: single tf32 product (hh). Stage = {A_HI, B_HI at E_OFF_B}.
static __device__ __forceinline__ void mma_chunk1(
    unsigned base, unsigned aRow, unsigned bRow,
    const unsigned colA[4], const unsigned colB[4], float acc[4][4][4])
{
    unsigned fa[4][4], fb[2][4];
#pragma unroll
    for (int k8 = 0; k8 < 4; ++k8) {
#pragma unroll
        for (int i = 0; i < 4; ++i)
            LDSM_X4(fa[i], base + aRow + 2048u * i + colA[k8]);
#pragma unroll
        for (int jp = 0; jp < 2; ++jp)
            LDSM_X4(fb[jp], base + E_OFF_B + bRow + 2048u * jp + colB[k8]);

#pragma unroll
        for (int i = 0; i < 4; ++i)
#pragma unroll
            for (int j = 0; j < 4; ++j)
                MMA_TF32(acc[i][j], fa[i], fb[j >> 1][(j & 1) * 2],
                         fb[j >> 1][(j & 1) * 2 + 1]);
    }
}

// online-softmax pair combine
static __device__ __forceinline__ void comb(float& m, float& s, float mo, float so) {
    float mn = fmaxf(m, mo);
    s = s * __expf(m - mn) + so * __expf(mo - mn);
    m = mn;
}

// ---------------------------------------------------------------------------
// compact: one block per batch; inclusive scan of mask -> idx list + count
// ---------------------------------------------------------------------------
__global__ __launch_bounds__(1024)
void compact_kernel(const int* __restrict__ mask)
{
    __shared__ int s[1024];
    const int b = blockIdx.x;
    const int t = threadIdx.x;
    const int mk = mask[b * YL + t];
    s[t] = mk;
    __syncthreads();
#pragma unroll
    for (int off = 1; off < 1024; off <<= 1) {
        int v = (t >= off) ? s[t - off] : 0;
        __syncthreads();
        s[t] += v;
        __syncthreads();
    }
    if (mk) g_idx[b][s[t] - 1] = t;
    if (t == 1023) g_cnt[b] = s[1023];
}

// ---------------------------------------------------------------------------
// gather: g_ys_c[b][j][:] = ys[b][idx[j]][:]; zero rows [cnt, nc_pad)
// ---------------------------------------------------------------------------
__global__ __launch_bounds__(256)
void gather_kernel(const float* __restrict__ ys)
{
    const int b = blockIdx.y;
    const int t = threadIdx.x;
    const int cnt = g_cnt[b];
    const int ncp = (cnt + 127) & ~127;
    for (int r = 0; r < 16; ++r) {
        const int j = blockIdx.x * 16 + r;
        if (j >= ncp) break;
        float4 v = make_float4(0.f, 0.f, 0.f, 0.f);
        if (j < cnt) {
            const int y = g_idx[b][j];
            v = *reinterpret_cast<const float4*>(ys + ((size_t)b * YL + y) * DD + t * 4);
        }
        *reinterpret_cast<float4*>(g_ys_c + ((size_t)b * YL + j) * DD + t * 4) = v;
    }
}

// ---------------------------------------------------------------------------
// zerofill: weight output region -> 0
// ---------------------------------------------------------------------------
__global__ __launch_bounds__(256)
void zerofill_kernel(float* __restrict__ w)
{
    const size_t i = ((size_t)blockIdx.x * 256 + threadIdx.x) * 16;
    float4 z = make_float4(0.f, 0.f, 0.f, 0.f);
#pragma unroll
    for (int q = 0; q < 4; ++q)
        *reinterpret_cast<float4*>(w + i + q * 4) = z;
}

// ---------------------------------------------------------------------------
// scores: xs @ ys_c^T (bf16 3x); raw scores -> g_scratch; stats -> g_stats
// ---------------------------------------------------------------------------
__global__ __launch_bounds__(384, 1)
void scores_tc_kernel(const float* __restrict__ xs)
{
    extern __shared__ char smem[];
    const unsigned sb = smem_u32(smem);
    const int t = threadIdx.x;
    const int wid = t >> 5;
    const int lane = t & 31;
    const int b = blockIdx.z;
    const int rowBase = blockIdx.y * 128;
    const int colBase = blockIdx.x * 128;

    const int cnt = g_cnt[b];
    const int ncp = (cnt + 127) & ~127;
    if (colBase >= ncp) return;            // uniform early exit, no barriers yet

    const float* A  = xs + (size_t)b * XL * DD + (size_t)rowBase * DD;
    const float* Bp = g_ys_c + (size_t)b * YL * DD + (size_t)colBase * DD;

    if (wid >= 8) {
        // ---------------- producer warps (8..11) ----------------
        const int pt = t - 256;   // 0..127

        int s = 0;
        for (int c = 0; c < 16; ++c) {          // 16 chunks of K=64
            char* st = smem + s * S_STAGE;
            const int k0 = c * 64;
            if (c >= 3) bar_sync(4 + s);
            // A tile: 128 rows x 64 floats; 16 float4 slots/thread
            {
                float4 v[16];
#pragma unroll
                for (int i = 0; i < 16; ++i) {
                    int sl = pt + i * 128;
                    int r  = sl >> 4;
                    int c4 = sl & 15;
                    v[i] = *reinterpret_cast<const float4*>(
                        A + (size_t)r * DD + k0 + c4 * 4);
                }
#pragma unroll
                for (int i = 0; i < 16; ++i) {
                    int sl = pt + i * 128;
                    int r  = sl >> 4;
                    int c4 = sl & 15;
                    unsigned off = (unsigned)r * 128u +
                                   (((unsigned)c4 * 8u) ^ (((unsigned)(r & 7)) << 4));
                    uint2 h, l;
                    split4_bf(v[i], h, l);
                    *reinterpret_cast<uint2*>(st + OFF_A_HI + off) = h;
                    *reinterpret_cast<uint2*>(st + OFF_A_LO + off) = l;
                }
            }
            // B tile
            {
                float4 v[16];
#pragma unroll
                for (int i = 0; i < 16; ++i) {
                    int sl = pt + i * 128;
                    int r  = sl >> 4;
                    int c4 = sl & 15;
                    v[i] = *reinterpret_cast<const float4*>(
                        Bp + (size_t)r * DD + k0 + c4 * 4);
                }
#pragma unroll
                for (int i = 0; i < 16; ++i) {
                    int sl = pt + i * 128;
                    int r  = sl >> 4;
                    int c4 = sl & 15;
                    unsigned off = (unsigned)r * 128u +
                                   (((unsigned)c4 * 8u) ^ (((unsigned)(r & 7)) << 4));
                    uint2 h, l;
                    split4_bf(v[i], h, l);
                    *reinterpret_cast<uint2*>(st + OFF_B_HI + off) = h;
                    *reinterpret_cast<uint2*>(st + OFF_B_LO + off) = l;
                }
            }
            __threadfence_block();
            bar_arrive(1 + s);
            s = (s == 2) ? 0 : s + 1;
        }
        return;
    }

    // ---------------- consumer warps (0..7) ----------------
    const int m0 = (wid & 1) * 64;
    const int n0 = (wid >> 1) * 32;

    const unsigned xr = (unsigned)(lane & 7) << 4;
    const unsigned rA = (unsigned)((lane & 7) + ((lane >> 3) & 1) * 8);
    const unsigned cA = (unsigned)((lane >> 4) << 4);
    const unsigned rB = (unsigned)((lane & 7) + ((lane >> 4) & 1) * 8);
    const unsigned cB = (unsigned)(((lane >> 3) & 1) << 4);
    const unsigned aRow = ((unsigned)m0 + rA) * 128u;
    const unsigned bRow = ((unsigned)n0 + rB) * 128u;
    unsigned colA[4], colB[4];
#pragma unroll
    for (int k16 = 0; k16 < 4; ++k16) {
        colA[k16] = ((unsigned)(k16 * 32) + cA) ^ xr;
        colB[k16] = ((unsigned)(k16 * 32) + cB) ^ xr;
    }

    float acc[4][4][4];
#pragma unroll
    for (int i = 0; i < 4; ++i)
#pragma unroll
        for (int j = 0; j < 4; ++j)
#pragma unroll
            for (int d = 0; d < 4; ++d) acc[i][j][d] = 0.0f;

    int s = 0;
    for (int c = 0; c < 16; ++c) {
        bar_sync(1 + s);
        mma_chunk3(sb + (unsigned)s * S_STAGE, aRow, bRow, colA, colB, acc);
        bar_arrive(4 + s);
        s = (s == 2) ? 0 : s + 1;
    }

    // epilogue: raw scores -> scratch (NEG_INF beyond cnt); per-row stats
    float2* stat = (float2*)(smem + S_OFF_STATS);   // [128][4]
    float* sc = g_scratch + (size_t)b * XL * YL + (size_t)rowBase * YL + colBase;
    const int g = lane >> 2;
    const int cp = (lane & 3) * 2;
    const int nwid = wid >> 1;
    const int lim = cnt - colBase;                  // valid cols in this tile

#pragma unroll
    for (int i = 0; i < 4; ++i) {
        const int rowL = m0 + 16 * i + g;
        float mL = NEG_INF, mH = NEG_INF;
        float sL = 0.0f, sH = 0.0f;
        float v0s[4], v1s[4], v2s[4], v3s[4];
#pragma unroll
        for (int j = 0; j < 4; ++j) {
            const int col = n0 + 8 * j + cp;
            const bool ok0 = col < lim;
            const bool ok1 = (col + 1) < lim;
            float v0 = ok0 ? acc[i][j][0] : NEG_INF;
            float v1 = ok1 ? acc[i][j][1] : NEG_INF;
            float v2 = ok0 ? acc[i][j][2] : NEG_INF;
            float v3 = ok1 ? acc[i][j][3] : NEG_INF;
            v0s[j] = v0; v1s[j] = v1; v2s[j] = v2; v3s[j] = v3;
            float2 w0; w0.x = v0; w0.y = v1;
            float2 w1; w1.x = v2; w1.y = v3;
            *reinterpret_cast<float2*>(sc + (size_t)rowL * YL + col) = w0;
            *reinterpret_cast<float2*>(sc + (size_t)(rowL + 8) * YL + col) = w1;
            mL = fmaxf(mL, fmaxf(v0, v1));
            mH = fmaxf(mH, fmaxf(v2, v3));
        }
#pragma unroll
        for (int j = 0; j < 4; ++j) {
            sL += __expf(v0s[j] - mL) + __expf(v1s[j] - mL);
            sH += __expf(v2s[j] - mH) + __expf(v3s[j] - mH);
        }
        // reduce across the 4 lanes sharing each row
#pragma unroll
        for (int d = 1; d < 4; d <<= 1) {
            float mo = __shfl_xor_sync(0xFFFFFFFFu, mL, d);
            float so = __shfl_xor_sync(0xFFFFFFFFu, sL, d);
            comb(mL, sL, mo, so);
            mo = __shfl_xor_sync(0xFFFFFFFFu, mH, d);
            so = __shfl_xor_sync(0xFFFFFFFFu, sH, d);
            comb(mH, sH, mo, so);
        }
        if ((lane & 3) == 0) {
            float2 v; v.x = mL; v.y = sL;
            stat[rowL * 4 + nwid] = v;
            v.x = mH; v.y = sH;
            stat[(rowL + 8) * 4 + nwid] = v;
        }
    }
    bar_sync_n(7, 256);                // consumer warps only
    if (t < 128) {
        float2 a = stat[t * 4 + 0];
#pragma unroll
        for (int q = 1; q < 4; ++q) {
            float2 o = stat[t * 4 + q];
            comb(a.x, a.y, o.x, o.y);
        }
        g_stats[b * XL + rowBase + t][blockIdx.x] = a;
    }
}

// ---------------------------------------------------------------------------
// reduce: fold active per-tile stats into per-row (max, 1/sum)
// ---------------------------------------------------------------------------
__global__ __launch_bounds__(256)
void reduce_stats_kernel()
{
    const int r = blockIdx.x * 256 + threadIdx.x;
    const int b = r >> 10;
    const int nt = (g_cnt[b] + 127) >> 7;
    float2 a = g_stats[r][0];
    for (int i = 1; i < nt; ++i) {
        float2 o = g_stats[r][i];
        comb(a.x, a.y, o.x, o.y);
    }
    float2 out; out.x = a.x; out.y = 1.0f / a.y;
    g_rowstats[r] = out;
}

// ---------------------------------------------------------------------------
// emb: softmax(scratch) @ ys_c, K = nc_pad (runtime), single tf32 product.
// Producers apply exp; bx==0 producers scatter weights to wout via g_idx.
// ---------------------------------------------------------------------------
__global__ __launch_bounds__(384, 1)
void emb_tc_kernel(float* __restrict__ emb, float* __restrict__ wout)
{
    extern __shared__ char smem[];
    const unsigned sb = smem_u32(smem);
    const int t = threadIdx.x;
    const int wid = t >> 5;
    const int lane = t & 31;
    const int b = blockIdx.z;
    const int rowBase = blockIdx.y * 128;   // x
    const int colBase = blockIdx.x * 128;   // d

    const int cnt = g_cnt[b];
    const int ncp = (cnt + 127) & ~127;
    const int nch = ncp >> 5;               // K chunks

    const float* A   = g_scratch + (size_t)b * XL * YL + (size_t)rowBase * YL;
    const float* Byb = g_ys_c + (size_t)b * YL * DD + colBase;

    if (wid >= 8) {
        // ---------------- producer warps ----------------
        const int pt = t - 256;   // 0..127
        const bool wb = (blockIdx.x == 0);
        int* idxs = (int*)(smem + E_OFF_IDX);
        if (wb) {
            for (int q = pt; q < cnt; q += 128) idxs[q] = g_idx[b][q];
            bar_sync_n(8, 128);
        }

        int lr[8], lc4[8];
        unsigned loff[8];
#pragma unroll
        for (int i = 0; i < 8; ++i) {
            int s = pt + i * 128;
            lr[i]  = s >> 3;
            lc4[i] = s & 7;
            loff[i] = (unsigned)lr[i] * 128u +
                      (((unsigned)lc4[i] * 16u) ^ (((unsigned)(lr[i] & 7)) << 4));
        }
        float2 rs[8];
#pragma unroll
        for (int i = 0; i < 8; ++i)
            rs[i] = g_rowstats[b * XL + rowBase + lr[i]];

        // B transpose-gather: thread owns d-col pt; 8 float4 of k values.
        unsigned tboff[8];
#pragma unroll
        for (int q = 0; q < 8; ++q)
            tboff[q] = (unsigned)pt * 128u +
                       (((unsigned)(q * 16)) ^ (((unsigned)(pt & 7)) << 4));

        float* wrow = wout + (size_t)b * XL * YL;

        float4 pa[8], pb[8];
#pragma unroll
        for (int i = 0; i < 8; ++i)
            pa[i] = *reinterpret_cast<const float4*>(A + (size_t)lr[i] * YL + lc4[i] * 4);
        {
            const float* bp = Byb + pt;
#pragma unroll
            for (int q = 0; q < 8; ++q) {
                pb[q].x = bp[(size_t)(q * 4 + 0) * DD];
                pb[q].y = bp[(size_t)(q * 4 + 1) * DD];
                pb[q].z = bp[(size_t)(q * 4 + 2) * DD];
                pb[q].w = bp[(size_t)(q * 4 + 3) * DD];
            }
        }

        int s = 0;
        for (int c = 0; c < nch; ++c) {
            char* st = smem + s * E_STAGE;
            const int k0c = c * 32;
            if (c >= 3) bar_sync(4 + s);
#pragma unroll
            for (int i = 0; i < 8; ++i) {
                float4 e;
                e.x = __expf(pa[i].x - rs[i].x) * rs[i].y;
                e.y = __expf(pa[i].y - rs[i].x) * rs[i].y;
                e.z = __expf(pa[i].z - rs[i].x) * rs[i].y;
                e.w = __expf(pa[i].w - rs[i].x) * rs[i].y;
                *reinterpret_cast<float4*>(st + loff[i]) = hi4(e);
                if (wb) {
                    const int cbase = k0c + lc4[i] * 4;
                    float* wr = wrow + (size_t)(rowBase + lr[i]) * YL;
                    if (cbase + 0 < cnt) wr[idxs[cbase + 0]] = e.x;
                    if (cbase + 1 < cnt) wr[idxs[cbase + 1]] = e.y;
                    if (cbase + 2 < cnt) wr[idxs[cbase + 2]] = e.z;
                    if (cbase + 3 < cnt) wr[idxs[cbase + 3]] = e.w;
                }
            }
#pragma unroll
            for (int q = 0; q < 8; ++q) {
                *reinterpret_cast<float4*>(st + E_OFF_B + tboff[q]) = hi4(pb[q]);
            }
            __threadfence_block();
            bar_arrive(1 + s);
            if (c < nch - 1) {
                const int k0 = (c + 1) * 32;
#pragma unroll
                for (int i = 0; i < 8; ++i)
                    pa[i] = *reinterpret_cast<const float4*>(A + (size_t)lr[i] * YL + k0 + lc4[i] * 4);
                const float* bp = Byb + (size_t)k0 * DD + pt;
#pragma unroll
                for (int q = 0; q < 8; ++q) {
                    pb[q].x = bp[(size_t)(q * 4 + 0) * DD];
                    pb[q].y = bp[(size_t)(q * 4 + 1) * DD];
                    pb[q].z = bp[(size_t)(q * 4 + 2) * DD];
                    pb[q].w = bp[(size_t)(q * 4 + 3) * DD];
                }
            }
            s = (s == 2) ? 0 : s + 1;
        }
        return;
    }

    // ---------------- consumer warps ----------------
    const int m0 = (wid & 1) * 64;
    const int n0 = (wid >> 1) * 32;

    const unsigned xr = (unsigned)(lane & 7) << 4;
    const unsigned rA = (unsigned)((lane & 7) + ((lane >> 3) & 1) * 8);
    const unsigned cA = (unsigned)((lane >> 4) << 4);
    const unsigned rB = (unsigned)((lane & 7) + ((lane >> 4) & 1) * 8);
    const unsigned cB = (unsigned)(((lane >> 3) & 1) << 4);
    const unsigned aRow = ((unsigned)m0 + rA) * 128u;
    const unsigned bRow = ((unsigned)n0 + rB) * 128u;
    unsigned colA[4], colB[4];
#pragma unroll
    for (int k8 = 0; k8 < 4; ++k8) {
        colA[k8] = ((unsigned)(k8 * 32) + cA) ^ xr;
        colB[k8] = ((unsigned)(k8 * 32) + cB) ^ xr;
    }

    float acc[4][4][4];
#pragma unroll
    for (int i = 0; i < 4; ++i)
#pragma unroll
        for (int j = 0; j < 4; ++j)
#pragma unroll
            for (int d = 0; d < 4; ++d) acc[i][j][d] = 0.0f;

    int s = 0;
    for (int c = 0; c < nch; ++c) {
        bar_sync(1 + s);
        mma_chunk1(sb + (unsigned)s * E_STAGE, aRow, bRow, colA, colB, acc);
        bar_arrive(4 + s);
        s = (s == 2) ? 0 : s + 1;
    }

    float* obase = emb + (size_t)b * XL * DD + colBase;
    const int g = lane >> 2;
    const int cp = (lane & 3) * 2;
#pragma unroll
    for (int i = 0; i < 4; ++i) {
        const int row = rowBase + m0 + 16 * i + g;
#pragma unroll
        for (int j = 0; j < 4; ++j) {
            const int col = n0 + 8 * j + cp;
            float2 v;
            v.x = acc[i][j][0];
            v.y = acc[i][j][1];
            *reinterpret_cast<float2*>(obase + (size_t)row * DD + col) = v;
            v.x = acc[i][j][2];
            v.y = acc[i][j][3];
            *reinterpret_cast<float2*>(obase + (size_t)(row + 8) * DD + col) = v;
        }
    }
}

// ---------------------------------------------------------------------------
extern "C" void kernel_launch(void* const* d_in, const int* in_sizes, int n_in,
                              void* d_out, int out_size)
{
    const float* xs   = (const float*)d_in[0];
    const float* ys   = (const float*)d_in[1];
    const int*   mask = (const int*)d_in[2];

    float* emb = (float*)d_out;                           // [B, XL, D]
    float* w   = (float*)d_out + (size_t)BB * XL * DD;    // [B, XL, YL]

    cudaFuncSetAttribute(scores_tc_kernel,
                         cudaFuncAttributeMaxDynamicSharedMemorySize, S_SMEM_BYTES);
    cudaFuncSetAttribute(emb_tc_kernel,
                         cudaFuncAttributeMaxDynamicSharedMemorySize, E_SMEM_BYTES);

    compact_kernel<<<BB, 1024>>>(mask);
    gather_kernel<<<dim3(64, BB), 256>>>(ys);
    zerofill_kernel<<<(BB * XL * (YL / 16)) / 256, 256>>>(w);
    scores_tc_kernel<<<dim3(8, 8, BB), 384, S_SMEM_BYTES>>>(xs);
    reduce_stats_kernel<<<(BB * XL) / 256, 256>>>();
    emb_tc_kernel<<<dim3(8, 8, BB), 384, E_SMEM_BYTES>>>(emb, w);
}